// round 12
// baseline (speedup 1.0000x reference)
#include <cuda_runtime.h>
#include <cuda_bf16.h>
#include <cstdint>

#define NTOK 8192
#define DDIM 1024
#define HDIM 2048
#define MI 1048576ULL

typedef __nv_bfloat16 bf16;

// ===================== scratch (static device globals) ======================
__device__ float g_keys[NTOK * DDIM];
__device__ float g_values[NTOK * DDIM];
__device__ float g_queries[NTOK * DDIM];
__device__ float g_hk[NTOK * HDIM];
__device__ float g_g0[HDIM * DDIM];
__device__ float g_g0b[HDIM * DDIM];
__device__ float g_g1[DDIM * HDIM];
__device__ float g_g1b[DDIM * HDIM];
__device__ float g_xpart[8 * 4 * DDIM];
__device__ float g_xmean[4 * DDIM];
__device__ float g_gpart[3 * DDIM];
__device__ float g_gates[3];

__device__ bf16 g_bfh[157 * MI];
__device__ bf16 g_bfl[157 * MI];

// offsets (elements) inside g_bfh/g_bfl
#define O_X    (0 * MI)
#define O_T1   (8 * MI)
#define O_KEY  (16 * MI)
#define O_KEYT (24 * MI)
#define O_Q    (32 * MI)
#define O_AQ   (40 * MI)   // 16Mi
#define O_WP   (56 * MI)   // W' = out_w @ mem_w1, [D][H], 2Mi
#define O_AK   (64 * MI)   // 16Mi
#define O_AKT  (80 * MI)   // 16Mi
#define O_DP   (96 * MI)
#define O_DPT  (104 * MI)
#define O_DHT  (112 * MI)  // 16Mi
#define O_KP1  (128 * MI)
#define O_KP2  (129 * MI)
#define O_VP1  (130 * MI)
#define O_VP2  (131 * MI)
#define O_QP1  (132 * MI)
#define O_QP2  (133 * MI)
#define O_OW   (134 * MI)
#define O_M0   (135 * MI)  // 2Mi
#define O_M1   (137 * MI)  // 2Mi
#define O_M1T  (139 * MI)  // 2Mi
#define O_T1B  (141 * MI)  // 8Mi (dead after proj2)
#define O_T1C  (149 * MI)  // 8Mi (dead after proj2)
#define O_DH   (141 * MI)  // 16Mi, reuses T1B+T1C region

#define DPC (2.0f / (float)((size_t)NTOK * DDIM))

// ===================== small helpers =======================================
static __device__ __forceinline__ float sigf(float x) {
    return 1.0f / (1.0f + __expf(-x));
}
static __device__ __forceinline__ float siluf(float x) { return x * sigf(x); }

static __device__ __forceinline__ void split1(float v, bf16& h, bf16& l) {
    h = __float2bfloat16(v);
    l = __float2bfloat16(v - __bfloat162float(h));
}
static __device__ __forceinline__ unsigned packu(bf16 a, bf16 b) {
    unsigned short x = *(unsigned short*)&a, y = *(unsigned short*)&b;
    return (unsigned)x | ((unsigned)y << 16);
}
static __device__ __forceinline__ uint32_t smem_u32(const void* p) {
    uint32_t a;
    asm("{ .reg .u64 t; cvta.to.shared.u64 t, %1; cvt.u32.u64 %0, t; }"
        : "=r"(a) : "l"(p));
    return a;
}

// cp.async / ldmatrix / mma wrappers (sm_80-compatible)
static __device__ __forceinline__ void cp16(uint32_t s, const void* g) {
    asm volatile("cp.async.cg.shared.global [%0], [%1], 16;" :: "r"(s), "l"(g));
}
static __device__ __forceinline__ void cp_commit() {
    asm volatile("cp.async.commit_group;" ::: "memory");
}
template <int N>
static __device__ __forceinline__ void cp_wait() {
    asm volatile("cp.async.wait_group %0;" :: "n"(N) : "memory");
}
static __device__ __forceinline__ void ldm4(uint32_t a, uint32_t& r0, uint32_t& r1,
                                            uint32_t& r2, uint32_t& r3) {
    asm volatile("ldmatrix.sync.aligned.m8n8.x4.shared.b16 {%0,%1,%2,%3}, [%4];"
                 : "=r"(r0), "=r"(r1), "=r"(r2), "=r"(r3) : "r"(a));
}
static __device__ __forceinline__ void mma16816(float* c, const uint32_t* a,
                                                const uint32_t* b) {
    asm volatile(
        "mma.sync.aligned.m16n8k16.row.col.f32.bf16.bf16.f32 "
        "{%0,%1,%2,%3}, {%4,%5,%6,%7}, {%8,%9}, {%0,%1,%2,%3};"
        : "+f"(c[0]), "+f"(c[1]), "+f"(c[2]), "+f"(c[3])
        : "r"(a[0]), "r"(a[1]), "r"(a[2]), "r"(a[3]), "r"(b[0]), "r"(b[1]));
}

// ===================== batched mma.sync GEMM ===============================
// Per z-slice: C[M,N] = sum_k A[m,k]*B[n,k]; A/B bf16 hi+lo rows with leading
// dims lda/ldb. CTA tile 128x128x64, 8 warps (64x32), bf16x3, 3-stage
// cp.async, single __syncthreads per stage. (R7-proven best config.)
// EPI: 0 none, 1 silu, 2 dpred ((v-aux)*DPC), 3 dh (v*silu'(aux)).
// WF32 writes fp32 (RAW ? pre-EPI : post-EPI); WBF writes post-EPI bf16 hi/lo.
#define BKG 64
#define RSB 144                       // 64 bf16 (128B) + 16B pad
#define TILE_B (128 * RSB)            // 18432
#define STAGE_B (4 * TILE_B)          // 73728
#define NSTAGE 3
#define GSMEM (NSTAGE * STAGE_B)      // 221184

struct GemmB {
    const bf16 *Ah, *Al, *Bh, *Bl;
    float* C;
    bf16 *Ch, *Cl;
    const float* aux;
};
struct GemmB3 { GemmB b[3]; };

template <int EPI, bool WF32, bool WBF, bool RAW>
__global__ __launch_bounds__(256, 1)
void mma_gemm(GemmB3 P, int M, int N, int K, int lda, int ldb)
{
    extern __shared__ char sm[];
    uint32_t sb = smem_u32(sm);
    const GemmB gp = P.b[blockIdx.z];
    const int t = threadIdx.x, lane = t & 31, wid = t >> 5;
    const int row0 = blockIdx.y * 128, col0 = blockIdx.x * 128;

    const bf16* gA0 = gp.Ah + (size_t)row0 * lda;
    const bf16* gA1 = gp.Al + (size_t)row0 * lda;
    const bf16* gB0 = gp.Bh + (size_t)col0 * ldb;
    const bf16* gB1 = gp.Bl + (size_t)col0 * ldb;

    const int r_ld = t >> 3, kc = t & 7;   // 32 rows x 8 16B-chunks per pass

    auto issue = [&](int s) {
        int k0 = s * BKG;
        uint32_t dst = sb + (s % NSTAGE) * STAGE_B + kc * 16;
        const bf16* a0 = gA0 + k0 + kc * 8;
        const bf16* a1 = gA1 + k0 + kc * 8;
        const bf16* b0 = gB0 + k0 + kc * 8;
        const bf16* b1 = gB1 + k0 + kc * 8;
#pragma unroll
        for (int j = 0; j < 4; j++) {
            int r = r_ld + 32 * j;
            cp16(dst + r * RSB, a0 + (size_t)r * lda);
            cp16(dst + TILE_B + r * RSB, a1 + (size_t)r * lda);
            cp16(dst + 2 * TILE_B + r * RSB, b0 + (size_t)r * ldb);
            cp16(dst + 3 * TILE_B + r * RSB, b1 + (size_t)r * ldb);
        }
        cp_commit();
    };

    const int wm = wid & 1, wn = wid >> 1;
    float acc[4][4][4];
#pragma unroll
    for (int i = 0; i < 4; i++)
#pragma unroll
        for (int j = 0; j < 4; j++)
#pragma unroll
            for (int r = 0; r < 4; r++) acc[i][j][r] = 0.0f;

    const int arow = wm * 64 + (lane & 15);
    const int acolh = (lane >> 4) * 16;
    const int brow = wn * 32 + (lane & 7) + ((lane >> 4) << 3);
    const int bcolh = ((lane >> 3) & 1) * 16;

    const int S = K / BKG;
    issue(0);
    issue(1);
    for (int s = 0; s < S; s++) {
        if (s + 1 < S) cp_wait<1>(); else cp_wait<0>();
        __syncthreads();
        if (s + 2 < S) issue(s + 2);

        uint32_t st = sb + (s % NSTAGE) * STAGE_B;
        uint32_t aAh = st, aAl = st + TILE_B;
        uint32_t aBh = st + 2 * TILE_B, aBl = st + 3 * TILE_B;
#pragma unroll
        for (int kb = 0; kb < 4; kb++) {
            uint32_t ah[4][4], al[4][4], bh[4][2], bl[4][2];
#pragma unroll
            for (int mi = 0; mi < 4; mi++) {
                uint32_t off = (uint32_t)(arow + mi * 16) * RSB + kb * 32 + acolh;
                ldm4(aAh + off, ah[mi][0], ah[mi][1], ah[mi][2], ah[mi][3]);
                ldm4(aAl + off, al[mi][0], al[mi][1], al[mi][2], al[mi][3]);
            }
#pragma unroll
            for (int jp = 0; jp < 2; jp++) {
                uint32_t off = (uint32_t)(brow + jp * 16) * RSB + kb * 32 + bcolh;
                uint32_t r0, r1, r2, r3;
                ldm4(aBh + off, r0, r1, r2, r3);
                bh[jp * 2][0] = r0; bh[jp * 2][1] = r1;
                bh[jp * 2 + 1][0] = r2; bh[jp * 2 + 1][1] = r3;
                ldm4(aBl + off, r0, r1, r2, r3);
                bl[jp * 2][0] = r0; bl[jp * 2][1] = r1;
                bl[jp * 2 + 1][0] = r2; bl[jp * 2 + 1][1] = r3;
            }
#pragma unroll
            for (int mi = 0; mi < 4; mi++)
#pragma unroll
                for (int nj = 0; nj < 4; nj++) {
                    mma16816(acc[mi][nj], ah[mi], bh[nj]);
                    mma16816(acc[mi][nj], ah[mi], bl[nj]);
                    mma16816(acc[mi][nj], al[mi], bh[nj]);
                }
        }
    }

    // epilogue
    const int grow = lane >> 2, gc2 = (lane & 3) * 2;
#pragma unroll
    for (int mi = 0; mi < 4; mi++) {
#pragma unroll
        for (int nj = 0; nj < 4; nj++) {
            int col = col0 + wn * 32 + nj * 8 + gc2;
#pragma unroll
            for (int h = 0; h < 2; h++) {
                size_t row = (size_t)(row0 + wm * 64 + mi * 16 + grow + h * 8);
                float r0 = acc[mi][nj][h * 2], r1 = acc[mi][nj][h * 2 + 1];
                float v0 = r0, v1 = r1;
                if (EPI == 1) { v0 = siluf(v0); v1 = siluf(v1); }
                if (EPI == 2) {
                    float2 a = *(const float2*)&gp.aux[row * (size_t)N + col];
                    v0 = (v0 - a.x) * DPC;
                    v1 = (v1 - a.y) * DPC;
                }
                if (EPI == 3) {
                    float2 a = *(const float2*)&gp.aux[row * (size_t)N + col];
                    float s;
                    s = sigf(a.x); v0 *= s * (1.0f + a.x * (1.0f - s));
                    s = sigf(a.y); v1 *= s * (1.0f + a.y * (1.0f - s));
                }
                if (WF32)
                    *(float2*)&gp.C[row * (size_t)N + col] =
                        RAW ? make_float2(r0, r1) : make_float2(v0, v1);
                if (WBF) {
                    bf16 h0, l0, h1, l1;
                    split1(v0, h0, l0);
                    split1(v1, h1, l1);
                    *(unsigned*)&gp.Ch[row * (size_t)N + col] = packu(h0, h1);
                    *(unsigned*)&gp.Cl[row * (size_t)N + col] = packu(l0, l1);
                }
            }
        }
    }
}

// ===================== conversion / elementwise kernels ====================

__global__ void conv_kernel(const float4* __restrict__ src,
                            bf16* __restrict__ hi, bf16* __restrict__ lo)
{
    int i = blockIdx.x * 256 + threadIdx.x;
    float4 v = src[i];
    bf16 h0, l0, h1, l1, h2, l2, h3, l3;
    split1(v.x, h0, l0); split1(v.y, h1, l1);
    split1(v.z, h2, l2); split1(v.w, h3, l3);
    ((uint2*)hi)[i] = make_uint2(packu(h0, h1), packu(h2, h3));
    ((uint2*)lo)[i] = make_uint2(packu(l0, l1), packu(l2, l3));
}

// z-batched conv of 3 equal-size fp32 arrays
struct Conv3 { const float4* s; bf16* h; bf16* l; };
struct Conv3P { Conv3 c[3]; };
__global__ void conv3_kernel(Conv3P P)
{
    Conv3 q = P.c[blockIdx.z];
    int i = blockIdx.x * 256 + threadIdx.x;
    float4 v = q.s[i];
    bf16 h0, l0, h1, l1, h2, l2, h3, l3;
    split1(v.x, h0, l0); split1(v.y, h1, l1);
    split1(v.z, h2, l2); split1(v.w, h3, l3);
    ((uint2*)q.h)[i] = make_uint2(packu(h0, h1), packu(h2, h3));
    ((uint2*)q.l)[i] = make_uint2(packu(l0, l1), packu(l2, l3));
}

// transpose + convert: src fp32 [R][C] -> dst hi/lo bf16 [C][R]
__global__ void trans_conv_kernel(const float* __restrict__ src,
                                  bf16* __restrict__ dhi, bf16* __restrict__ dlo,
                                  int R, int C)
{
    __shared__ float tile[32][33];
    int tx = threadIdx.x, ty = threadIdx.y;   // 16 x 8
    int r0 = blockIdx.y * 32, c0 = blockIdx.x * 32;
#pragma unroll
    for (int i = 0; i < 4; i++) {
        int r = ty + i * 8;
        float2 v = *(const float2*)&src[(size_t)(r0 + r) * C + c0 + tx * 2];
        tile[r][tx * 2] = v.x;
        tile[r][tx * 2 + 1] = v.y;
    }
    __syncthreads();
#pragma unroll
    for (int i = 0; i < 4; i++) {
        int c = ty + i * 8;
        float v0 = tile[tx * 2][c], v1 = tile[tx * 2 + 1][c];
        bf16 h0, l0, h1, l1;
        split1(v0, h0, l0); split1(v1, h1, l1);
        size_t o = (size_t)(c0 + c) * R + r0 + tx * 2;
        *(unsigned*)&dhi[o] = packu(h0, h1);
        *(unsigned*)&dlo[o] = packu(l0, l1);
    }
}

// bf16 hi/lo pair transpose: src [R][C] -> dst [C][R]
__global__ void trans2_bf16_kernel(const bf16* __restrict__ sh,
                                   const bf16* __restrict__ sl,
                                   bf16* __restrict__ dh_, bf16* __restrict__ dl_,
                                   int R, int C)
{
    __shared__ bf16 tile[32][34];
    int tx = threadIdx.x, ty = threadIdx.y;   // 16 x 8
    int r0 = blockIdx.y * 32, c0 = blockIdx.x * 32;
#pragma unroll
    for (int i = 0; i < 4; i++) {
        int r = ty + i * 8;
        unsigned v = *(const unsigned*)&sh[(size_t)(r0 + r) * C + c0 + tx * 2];
        tile[r][tx * 2] = ((bf16*)&v)[0];
        tile[r][tx * 2 + 1] = ((bf16*)&v)[1];
    }
    __syncthreads();
#pragma unroll
    for (int i = 0; i < 4; i++) {
        int c = ty + i * 8;
        *(unsigned*)&dh_[(size_t)(c0 + c) * R + r0 + tx * 2] =
            packu(tile[tx * 2][c], tile[tx * 2 + 1][c]);
    }
    __syncthreads();
#pragma unroll
    for (int i = 0; i < 4; i++) {
        int r = ty + i * 8;
        unsigned v = *(const unsigned*)&sl[(size_t)(r0 + r) * C + c0 + tx * 2];
        tile[r][tx * 2] = ((bf16*)&v)[0];
        tile[r][tx * 2 + 1] = ((bf16*)&v)[1];
    }
    __syncthreads();
#pragma unroll
    for (int i = 0; i < 4; i++) {
        int c = ty + i * 8;
        *(unsigned*)&dl_[(size_t)(c0 + c) * R + r0 + tx * 2] =
            packu(tile[tx * 2][c], tile[tx * 2 + 1][c]);
    }
}

template <bool WF32>
__global__ void l2norm_kernel(float* __restrict__ x,
                              bf16* __restrict__ hi, bf16* __restrict__ lo)
{
    float4* p = (float4*)(x + (size_t)blockIdx.x * DDIM);
    int t = threadIdx.x;
    float4 v = p[t];
    float ss = v.x * v.x + v.y * v.y + v.z * v.z + v.w * v.w;
    __shared__ float red[8];
#pragma unroll
    for (int o = 16; o; o >>= 1) ss += __shfl_xor_sync(~0u, ss, o);
    if ((t & 31) == 0) red[t >> 5] = ss;
    __syncthreads();
    if (t < 8) {
        float s2 = red[t];
#pragma unroll
        for (int o = 4; o; o >>= 1) s2 += __shfl_xor_sync(0xffu, s2, o);
        if (t == 0) red[0] = s2;
    }
    __syncthreads();
    float scale = 1.0f / fmaxf(sqrtf(red[0]), 1e-12f);
    v.x *= scale; v.y *= scale; v.z *= scale; v.w *= scale;
    if (WF32) p[t] = v;
    size_t i = (size_t)blockIdx.x * 256 + t;
    bf16 h0, l0, h1, l1, h2, l2, h3, l3;
    split1(v.x, h0, l0); split1(v.y, h1, l1);
    split1(v.z, h2, l2); split1(v.w, h3, l3);
    ((uint2*)hi)[i] = make_uint2(packu(h0, h1), packu(h2, h3));
    ((uint2*)lo)[i] = make_uint2(packu(l0, l1), packu(l2, l3));
}

// x partial mean: grid (16, 8). xpart[sy][idx] = sum over 256 S entries.
__global__ void xmean_part_kernel(const float* __restrict__ x, float* __restrict__ xp)
{
    int idx = blockIdx.x * 256 + threadIdx.x;   // 0..4095 (b*1024+d)
    int sy = blockIdx.y;
    int b = idx >> 10, d = idx & 1023;
    const float* p = x + ((size_t)b * 2048 + sy * 256) * DDIM + d;
    float s = 0.0f;
#pragma unroll 8
    for (int ss = 0; ss < 256; ss++) s += p[(size_t)ss * DDIM];
    xp[sy * 4096 + idx] = s;
}

__global__ void xmean_fin_kernel(const float* __restrict__ xp, float* __restrict__ xm)
{
    int idx = blockIdx.x * 256 + threadIdx.x;
    float s = 0.0f;
#pragma unroll
    for (int j = 0; j < 8; j++) s += xp[j * 4096 + idx];
    xm[idx] = s * (1.0f / 2048.0f);
}

// warp-per-(gate, j): part[g*1024+j] = sum_b sigmoid(xm[b].W[j] + bias[j])
__global__ void gate_partial_kernel(
    const float* __restrict__ xm,
    const float* __restrict__ gdw, const float* __restrict__ gdb,
    const float* __restrict__ glw, const float* __restrict__ glb,
    const float* __restrict__ gmw, const float* __restrict__ gmb,
    float* __restrict__ part)
{
    int w = (blockIdx.x * 256 + threadIdx.x) >> 5;   // 0..3071
    int lane = threadIdx.x & 31;
    int g = w >> 10, j = w & 1023;
    const float* W = (g == 0) ? gdw : (g == 1) ? glw : gmw;
    const float* bias = (g == 0) ? gdb : (g == 1) ? glb : gmb;
    const float4* wr = (const float4*)(W + (size_t)j * DDIM);
    float bj = bias[j];
    float acc = 0.0f;
#pragma unroll
    for (int b = 0; b < 4; b++) {
        const float4* xr = (const float4*)(xm + b * DDIM);
        float s = 0.0f;
#pragma unroll
        for (int i = 0; i < 8; i++) {
            float4 a = xr[lane + 32 * i];
            float4 ww = wr[lane + 32 * i];
            s += a.x * ww.x + a.y * ww.y + a.z * ww.z + a.w * ww.w;
        }
#pragma unroll
        for (int o = 16; o; o >>= 1) s += __shfl_xor_sync(~0u, s, o);
        if (lane == 0) acc += sigf(s + bj);
    }
    if (lane == 0) part[g * 1024 + j] = acc;
}

// gates[g] = mean over 4*1024. grid 3 blocks x 256 threads.
__global__ void gate_final_kernel(const float* __restrict__ part, float* __restrict__ gates)
{
    int g = blockIdx.x, t = threadIdx.x;
    float v = part[g * 1024 + t] + part[g * 1024 + 256 + t]
            + part[g * 1024 + 512 + t] + part[g * 1024 + 768 + t];
    __shared__ float red[8];
#pragma unroll
    for (int o = 16; o; o >>= 1) v += __shfl_xor_sync(~0u, v, o);
    if ((t & 31) == 0) red[t >> 5] = v;
    __syncthreads();
    if (t < 8) {
        float s2 = red[t];
#pragma unroll
        for (int o = 4; o; o >>= 1) s2 += __shfl_xor_sync(0xffu, s2, o);
        if (t == 0) gates[g] = s2 * (1.0f / 4096.0f);
    }
}

__global__ void update_kernel(
    const float4* __restrict__ w0, const float4* __restrict__ w1,
    const float4* __restrict__ m0, const float4* __restrict__ m1,
    const float4* __restrict__ gg0, const float4* __restrict__ gg0b,
    const float4* __restrict__ gg1, const float4* __restrict__ gg1b,
    const float* __restrict__ gates, float4* __restrict__ out4)
{
    const int HD4 = HDIM * DDIM / 4;
    int i = blockIdx.x * 256 + threadIdx.x;
    float alpha = gates[0], theta = gates[1], eta = gates[2];
    float oma = 1.0f - alpha;
    if (i < HD4) {
        float4 ga = gg0[i], gb = gg0b[i], m = m0[i], w = w0[i], nm, nw;
        nm.x = eta * m.x - theta * (ga.x + gb.x); nw.x = oma * w.x + nm.x;
        nm.y = eta * m.y - theta * (ga.y + gb.y); nw.y = oma * w.y + nm.y;
        nm.z = eta * m.z - theta * (ga.z + gb.z); nw.z = oma * w.z + nm.z;
        nm.w = eta * m.w - theta * (ga.w + gb.w); nw.w = oma * w.w + nm.w;
        out4[2097152 + i] = nw;
        out4[3145728 + i] = nm;
    } else {
        int j = i - HD4;
        float4 ga = gg1[j], gb = gg1b[j], m = m1[j], w = w1[j], nm, nw;
        nm.x = eta * m.x - theta * (ga.x + gb.x); nw.x = oma * w.x + nm.x;
        nm.y = eta * m.y - theta * (ga.y + gb.y); nw.y = oma * w.y + nm.y;
        nm.z = eta * m.z - theta * (ga.z + gb.z); nw.z = oma * w.z + nm.z;
        nm.w = eta * m.w - theta * (ga.w + gb.w); nw.w = oma * w.w + nm.w;
        out4[2621440 + j] = nw;
        out4[3670016 + j] = nm;
    }
}

// ===================== host ================================================

static GemmB3 mk1(const bf16* Ah, const bf16* Al, const bf16* Bh, const bf16* Bl,
                  float* C, bf16* Ch, bf16* Cl, const float* aux = nullptr)
{
    GemmB3 p{};
    p.b[0] = {Ah, Al, Bh, Bl, C, Ch, Cl, aux};
    return p;
}

extern "C" void kernel_launch(void* const* d_in, const int* in_sizes, int n_in,
                              void* d_out, int out_size)
{
    (void)in_sizes; (void)n_in; (void)out_size;
    const float* x      = (const float*)d_in[0];
    const float* kp_w1  = (const float*)d_in[1];
    const float* kp_w2  = (const float*)d_in[2];
    const float* vp_w1  = (const float*)d_in[3];
    const float* vp_w2  = (const float*)d_in[4];
    const float* qp_w1  = (const float*)d_in[5];
    const float* qp_w2  = (const float*)d_in[6];
    const float* gd_w   = (const float*)d_in[7];
    const float* gd_b   = (const float*)d_in[8];
    const float* gl_w   = (const float*)d_in[9];
    const float* gl_b   = (const float*)d_in[10];
    const float* gm_w   = (const float*)d_in[11];
    const float* gm_b   = (const float*)d_in[12];
    const float* mem_w0 = (const float*)d_in[13];
    const float* mem_w1 = (const float*)d_in[14];
    const float* mom0   = (const float*)d_in[15];
    const float* mom1   = (const float*)d_in[16];
    const float* out_w  = (const float*)d_in[17];
    float* out = (float*)d_out;

    float *keys, *values, *queries, *hk, *gg0, *gg0b, *gg1, *gg1b;
    float *xpart, *xmean, *gpart, *gates;
    bf16 *bh, *bl;
    cudaGetSymbolAddress((void**)&keys, g_keys);
    cudaGetSymbolAddress((void**)&values, g_values);
    cudaGetSymbolAddress((void**)&queries, g_queries);
    cudaGetSymbolAddress((void**)&hk, g_hk);
    cudaGetSymbolAddress((void**)&gg0, g_g0);
    cudaGetSymbolAddress((void**)&gg0b, g_g0b);
    cudaGetSymbolAddress((void**)&gg1, g_g1);
    cudaGetSymbolAddress((void**)&gg1b, g_g1b);
    cudaGetSymbolAddress((void**)&xpart, g_xpart);
    cudaGetSymbolAddress((void**)&xmean, g_xmean);
    cudaGetSymbolAddress((void**)&gpart, g_gpart);
    cudaGetSymbolAddress((void**)&gates, g_gates);
    cudaGetSymbolAddress((void**)&bh, g_bfh);
    cudaGetSymbolAddress((void**)&bl, g_bfl);

    cudaFuncSetAttribute(mma_gemm<1, false, true, false>, cudaFuncAttributeMaxDynamicSharedMemorySize, GSMEM);
    cudaFuncSetAttribute(mma_gemm<1, true, false, false>, cudaFuncAttributeMaxDynamicSharedMemorySize, GSMEM);
    cudaFuncSetAttribute(mma_gemm<0, false, true, false>, cudaFuncAttributeMaxDynamicSharedMemorySize, GSMEM);
    cudaFuncSetAttribute(mma_gemm<0, true, false, false>, cudaFuncAttributeMaxDynamicSharedMemorySize, GSMEM);
    cudaFuncSetAttribute(mma_gemm<1, true, true, true>, cudaFuncAttributeMaxDynamicSharedMemorySize, GSMEM);
    cudaFuncSetAttribute(mma_gemm<2, false, true, false>, cudaFuncAttributeMaxDynamicSharedMemorySize, GSMEM);
    cudaFuncSetAttribute(mma_gemm<3, false, true, false>, cudaFuncAttributeMaxDynamicSharedMemorySize, GSMEM);

    // one-time stream/event resources (no device-memory allocation)
    static cudaStream_t s1 = nullptr;
    static cudaEvent_t evRoot, evW1, evW2, evWM, evW1T, evG, evKQ, evKT, evDP,
        evG1, evEnd;
    if (s1 == nullptr) {
        cudaStreamCreateWithFlags(&s1, cudaStreamNonBlocking);
        cudaEventCreateWithFlags(&evRoot, cudaEventDisableTiming);
        cudaEventCreateWithFlags(&evW1, cudaEventDisableTiming);
        cudaEventCreateWithFlags(&evW2, cudaEventDisableTiming);
        cudaEventCreateWithFlags(&evWM, cudaEventDisableTiming);
        cudaEventCreateWithFlags(&evW1T, cudaEventDisableTiming);
        cudaEventCreateWithFlags(&evG, cudaEventDisableTiming);
        cudaEventCreateWithFlags(&evKQ, cudaEventDisableTiming);
        cudaEventCreateWithFlags(&evKT, cudaEventDisableTiming);
        cudaEventCreateWithFlags(&evDP, cudaEventDisableTiming);
        cudaEventCreateWithFlags(&evG1, cudaEventDisableTiming);
        cudaEventCreateWithFlags(&evEnd, cudaEventDisableTiming);
    }

    dim3 blk(256);
    dim3 ttb(16, 8);

    // ---- fork side stream off the capture-origin (default) stream ----
    cudaEventRecord(evRoot, 0);
    cudaStreamWaitEvent(s1, evRoot, 0);

    // stream0: x conversion
    conv_kernel<<<8192, 256>>>((const float4*)x, bh + O_X, bl + O_X);

    // s1: weight conversions + gates
    {
        Conv3P p{};
        p.c[0] = {(const float4*)kp_w1, bh + O_KP1, bl + O_KP1};
        p.c[1] = {(const float4*)vp_w1, bh + O_VP1, bl + O_VP1};
        p.c[2] = {(const float4*)qp_w1, bh + O_QP1, bl + O_QP1};
        conv3_kernel<<<dim3(1024, 1, 3), 256, 0, s1>>>(p);
    }
    cudaEventRecord(evW1, s1);
    xmean_part_kernel<<<dim3(16, 8), 256, 0, s1>>>(x, xpart);
    xmean_fin_kernel<<<16, 256, 0, s1>>>(xpart, xmean);
    gate_partial_kernel<<<384, 256, 0, s1>>>(xmean, gd_w, gd_b, gl_w, gl_b,
                                             gm_w, gm_b, gpart);

    // stream0: projections layer 1 (z=3)
    cudaStreamWaitEvent(0, evW1, 0);
    {
        GemmB3 p{};
        p.b[0] = {bh + O_X, bl + O_X, bh + O_KP1, bl + O_KP1, nullptr, bh + O_T1, bl + O_T1, nullptr};
        p.b[1] = {bh + O_X, bl + O_X, bh + O_VP1, bl + O_VP1, nullptr, bh + O_T1B, bl + O_T1B, nullptr};
        p.b[2] = {bh + O_X, bl + O_X, bh + O_QP1, bl + O_QP1, nullptr, bh + O_T1C, bl + O_T1C, nullptr};
        mma_gemm<1, false, true, false><<<dim3(8, 64, 3), blk, GSMEM>>>(p, NTOK, DDIM, DDIM, DDIM, DDIM);
    }

    // s1: rest of gates + remaining conversions
    gate_final_kernel<<<3, 256, 0, s1>>>(gpart, gates);
    cudaEventRecord(evG, s1);
    {
        Conv3P p{};
        p.c[0] = {(const float4*)kp_w2, bh + O_KP2, bl + O_KP2};
        p.c[1] = {(const float4*)vp_w2, bh + O_VP2, bl + O_VP2};
        p.c[2] = {(const float4*)qp_w2, bh + O_QP2, bl + O_QP2};
        conv3_kernel<<<dim3(1024, 1, 3), 256, 0, s1>>>(p);
    }
    cudaEventRecord(evW2, s1);
    conv_kernel<<<2048, 256, 0, s1>>>((const float4*)mem_w0, bh + O_M0, bl + O_M0);
    conv_kernel<<<2048, 256, 0, s1>>>((const float4*)mem_w1, bh + O_M1, bl + O_M1);
    conv_kernel<<<1024, 256, 0, s1>>>((const float4*)out_w, bh + O_OW, bl + O_OW);
    cudaEventRecord(evWM, s1);
    trans_conv_kernel<<<dim3(HDIM / 32, DDIM / 32), ttb, 0, s1>>>(
        mem_w1, bh + O_M1T, bl + O_M1T, DDIM, HDIM);   // w1T [H][D]
    cudaEventRecord(evW1T, s1);

    // s1: W' = out_w @ mem_w1  ([D][H], K=D); out = aq @ W'^T later
    mma_gemm<0, false, true, false><<<dim3(16, 8, 1), blk, GSMEM, s1>>>(
        mk1(bh + O_OW, bl + O_OW, bh + O_M1T, bl + O_M1T,
            nullptr, bh + O_WP, bl + O_WP),
        DDIM, HDIM, DDIM, DDIM, DDIM);

    // stream0: projections layer 2 (z=3), l2norms
    cudaStreamWaitEvent(0, evW2, 0);
    {
        GemmB3 p{};
        p.b[0] = {bh + O_T1, bl + O_T1, bh + O_KP2, bl + O_KP2, keys, nullptr, nullptr, nullptr};
        p.b[1] = {bh + O_T1B, bl + O_T1B, bh + O_VP2, bl + O_VP2, values, nullptr, nullptr, nullptr};
        p.b[2] = {bh + O_T1C, bl + O_T1C, bh + O_QP2, bl + O_QP2, queries, nullptr, nullptr, nullptr};
        mma_gemm<1, true, false, false><<<dim3(8, 64, 3), blk, GSMEM>>>(p, NTOK, DDIM, DDIM, DDIM, DDIM);
    }
    l2norm_kernel<false><<<NTOK, 256>>>(keys, bh + O_KEY, bl + O_KEY);
    l2norm_kernel<false><<<NTOK, 256>>>(queries, bh + O_Q, bl + O_Q);
    cudaEventRecord(evKQ, 0);

    // s1: keysT (bf16 transpose of KEY) + q-chain (aq -> out via W')
    cudaStreamWaitEvent(s1, evKQ, 0);
    trans2_bf16_kernel<<<dim3(DDIM / 32, NTOK / 32), ttb, 0, s1>>>(
        bh + O_KEY, bl + O_KEY, bh + O_KEYT, bl + O_KEYT, NTOK, DDIM);
    cudaEventRecord(evKT, s1);
    mma_gemm<1, false, true, false><<<dim3(16, 64, 1), blk, GSMEM, s1>>>(
        mk1(bh + O_Q, bl + O_Q, bh + O_M0, bl + O_M0, nullptr, bh + O_AQ, bl + O_AQ),
        NTOK, HDIM, DDIM, DDIM, DDIM);
    mma_gemm<0, true, false, false><<<dim3(8, 64, 1), blk, GSMEM, s1>>>(
        mk1(bh + O_AQ, bl + O_AQ, bh + O_WP, bl + O_WP, out, nullptr, nullptr),
        NTOK, DDIM, HDIM, HDIM, HDIM);
    cudaEventRecord(evEnd, s1);

    // stream0: loss forward on keys (fused epilogues)
    cudaStreamWaitEvent(0, evWM, 0);
    // hk GEMM: writes raw hk fp32 + silu'd AK bf16 in one pass
    mma_gemm<1, true, true, true><<<dim3(16, 64, 1), blk, GSMEM>>>(
        mk1(bh + O_KEY, bl + O_KEY, bh + O_M0, bl + O_M0, hk, bh + O_AK, bl + O_AK),
        NTOK, HDIM, DDIM, DDIM, DDIM);
    trans2_bf16_kernel<<<dim3(HDIM / 32, NTOK / 32), ttb>>>(
        bh + O_AK, bl + O_AK, bh + O_AKT, bl + O_AKT, NTOK, HDIM);
    // pred GEMM with fused dpred epilogue: DP = (ak@w1 - values)*c, bf16 hi/lo
    mma_gemm<2, false, true, false><<<dim3(8, 64, 1), blk, GSMEM>>>(
        mk1(bh + O_AK, bl + O_AK, bh + O_M1, bl + O_M1, nullptr,
            bh + O_DP, bl + O_DP, values),
        NTOK, DDIM, HDIM, HDIM, HDIM);
    trans2_bf16_kernel<<<dim3(DDIM / 32, NTOK / 32), ttb>>>(
        bh + O_DP, bl + O_DP, bh + O_DPT, bl + O_DPT, NTOK, DDIM);
    cudaEventRecord(evDP, 0);

    // s1 (after q-chain): g1[D,H] = dpredT . akT  (split-K 2 via z)
    cudaStreamWaitEvent(s1, evDP, 0);
    {
        GemmB3 p{};
        p.b[0] = {bh + O_DPT, bl + O_DPT, bh + O_AKT, bl + O_AKT, gg1, nullptr, nullptr, nullptr};
        p.b[1] = {bh + O_DPT + NTOK / 2, bl + O_DPT + NTOK / 2,
                  bh + O_AKT + NTOK / 2, bl + O_AKT + NTOK / 2, gg1b, nullptr, nullptr, nullptr};
        mma_gemm<0, true, false, false><<<dim3(16, 8, 2), blk, GSMEM, s1>>>(
            p, DDIM, HDIM, NTOK / 2, NTOK, NTOK);
    }
    cudaEventRecord(evG1, s1);

    // stream0: da GEMM with fused dh epilogue: DH = (dp @ w1T) * silu'(hk)
    cudaStreamWaitEvent(0, evW1T, 0);
    mma_gemm<3, false, true, false><<<dim3(16, 64, 1), blk, GSMEM>>>(
        mk1(bh + O_DP, bl + O_DP, bh + O_M1T, bl + O_M1T, nullptr,
            bh + O_DH, bl + O_DH, hk),
        NTOK, HDIM, DDIM, DDIM, DDIM);
    trans2_bf16_kernel<<<dim3(HDIM / 32, NTOK / 32), ttb>>>(
        bh + O_DH, bl + O_DH, bh + O_DHT, bl + O_DHT, NTOK, HDIM);
    // g0[H,D] = dhT . keysT    (K = NTOK, split-K 2 via z)
    cudaStreamWaitEvent(0, evKT, 0);
    {
        GemmB3 p{};
        p.b[0] = {bh + O_DHT, bl + O_DHT, bh + O_KEYT, bl + O_KEYT, gg0, nullptr, nullptr, nullptr};
        p.b[1] = {bh + O_DHT + NTOK / 2, bl + O_DHT + NTOK / 2,
                  bh + O_KEYT + NTOK / 2, bl + O_KEYT + NTOK / 2, gg0b, nullptr, nullptr, nullptr};
        mma_gemm<0, true, false, false><<<dim3(8, 16, 2), blk, GSMEM>>>(
            p, HDIM, DDIM, NTOK / 2, NTOK, NTOK);
    }

    // ---- weight / momentum update (needs gates, g0, g1) ----
    cudaStreamWaitEvent(0, evG, 0);
    cudaStreamWaitEvent(0, evG1, 0);
    update_kernel<<<2 * HDIM * DDIM / 4 / 256, 256>>>(
        (const float4*)mem_w0, (const float4*)mem_w1,
        (const float4*)mom0, (const float4*)mom1,
        (const float4*)gg0, (const float4*)gg0b,
        (const float4*)gg1, (const float4*)gg1b, gates, (float4*)out);

    // ---- join side stream back into the origin stream ----
    cudaStreamWaitEvent(0, evEnd, 0);
}

// round 13
// speedup vs baseline: 1.0261x; 1.0261x over previous
#include <cuda_runtime.h>
#include <cuda_bf16.h>
#include <cstdint>

#define NTOK 8192
#define DDIM 1024
#define HDIM 2048
#define MI 1048576ULL

typedef __nv_bfloat16 bf16;

// ===================== scratch (static device globals) ======================
__device__ float g_keys[NTOK * DDIM];
__device__ float g_values[NTOK * DDIM];
__device__ float g_queries[NTOK * DDIM];
__device__ float g_hk[NTOK * HDIM];
__device__ float g_pred[NTOK * DDIM];
__device__ float g_da[NTOK * HDIM];
__device__ float g_g0[HDIM * DDIM];
__device__ float g_g0b[HDIM * DDIM];
__device__ float g_g1[DDIM * HDIM];
__device__ float g_g1b[DDIM * HDIM];
__device__ float g_xpart[8 * 4 * DDIM];
__device__ float g_xmean[4 * DDIM];
__device__ float g_gpart[3 * DDIM];
__device__ float g_gates[3];

__device__ bf16 g_bfh[157 * MI];
__device__ bf16 g_bfl[157 * MI];

// offsets (elements) inside g_bfh/g_bfl
#define O_X    (0 * MI)
#define O_T1   (8 * MI)
#define O_KEY  (16 * MI)
#define O_KEYT (24 * MI)
#define O_Q    (32 * MI)
#define O_AQ   (40 * MI)   // 16Mi
#define O_WP   (56 * MI)   // W' = out_w @ mem_w1, [D][H], 2Mi
#define O_AK   (64 * MI)   // 16Mi
#define O_AKT  (80 * MI)   // 16Mi
#define O_DP   (96 * MI)
#define O_DPT  (104 * MI)
#define O_DHT  (112 * MI)  // 16Mi
#define O_KP1  (128 * MI)
#define O_KP2  (129 * MI)
#define O_VP1  (130 * MI)
#define O_VP2  (131 * MI)
#define O_QP1  (132 * MI)
#define O_QP2  (133 * MI)
#define O_OW   (134 * MI)
#define O_M0   (135 * MI)  // 2Mi
#define O_M1   (137 * MI)  // 2Mi
#define O_M1T  (139 * MI)  // 2Mi
#define O_T1B  (141 * MI)  // 8Mi
#define O_T1C  (149 * MI)  // 8Mi

// ===================== small helpers =======================================
static __device__ __forceinline__ float sigf(float x) {
    return 1.0f / (1.0f + __expf(-x));
}
static __device__ __forceinline__ float siluf(float x) { return x * sigf(x); }

static __device__ __forceinline__ void split1(float v, bf16& h, bf16& l) {
    h = __float2bfloat16(v);
    l = __float2bfloat16(v - __bfloat162float(h));
}
static __device__ __forceinline__ unsigned packu(bf16 a, bf16 b) {
    unsigned short x = *(unsigned short*)&a, y = *(unsigned short*)&b;
    return (unsigned)x | ((unsigned)y << 16);
}
static __device__ __forceinline__ uint32_t smem_u32(const void* p) {
    uint32_t a;
    asm("{ .reg .u64 t; cvta.to.shared.u64 t, %1; cvt.u32.u64 %0, t; }"
        : "=r"(a) : "l"(p));
    return a;
}

// cp.async / ldmatrix / mma wrappers (sm_80-compatible)
static __device__ __forceinline__ void cp16(uint32_t s, const void* g) {
    asm volatile("cp.async.cg.shared.global [%0], [%1], 16;" :: "r"(s), "l"(g));
}
static __device__ __forceinline__ void cp_commit() {
    asm volatile("cp.async.commit_group;" ::: "memory");
}
template <int N>
static __device__ __forceinline__ void cp_wait() {
    asm volatile("cp.async.wait_group %0;" :: "n"(N) : "memory");
}
static __device__ __forceinline__ void ldm4(uint32_t a, uint32_t& r0, uint32_t& r1,
                                            uint32_t& r2, uint32_t& r3) {
    asm volatile("ldmatrix.sync.aligned.m8n8.x4.shared.b16 {%0,%1,%2,%3}, [%4];"
                 : "=r"(r0), "=r"(r1), "=r"(r2), "=r"(r3) : "r"(a));
}
static __device__ __forceinline__ void mma16816(float* c, const uint32_t* a,
                                                const uint32_t* b) {
    asm volatile(
        "mma.sync.aligned.m16n8k16.row.col.f32.bf16.bf16.f32 "
        "{%0,%1,%2,%3}, {%4,%5,%6,%7}, {%8,%9}, {%0,%1,%2,%3};"
        : "+f"(c[0]), "+f"(c[1]), "+f"(c[2]), "+f"(c[3])
        : "r"(a[0]), "r"(a[1]), "r"(a[2]), "r"(a[3]), "r"(b[0]), "r"(b[1]));
}

// ===================== batched mma.sync GEMM ===============================
// Per z-slice: C[M,N] = sum_k A[m,k]*B[n,k]; A/B bf16 hi+lo rows with leading
// dims lda/ldb. CTA tile 128x128x64, 8 warps (64x32), bf16x3, 3-stage
// cp.async, single __syncthreads per stage. (R7-proven best config.)
#define BKG 64
#define RSB 144                       // 64 bf16 (128B) + 16B pad
#define TILE_B (128 * RSB)            // 18432
#define STAGE_B (4 * TILE_B)          // 73728
#define NSTAGE 3
#define GSMEM (NSTAGE * STAGE_B)      // 221184

struct GemmB {
    const bf16 *Ah, *Al, *Bh, *Bl;
    float* C;
    bf16 *Ch, *Cl;
};
struct GemmB3 { GemmB b[3]; };

template <int EPI, bool WF32, bool WBF>
__global__ __launch_bounds__(256, 1)
void mma_gemm(GemmB3 P, int M, int N, int K, int lda, int ldb)
{
    extern __shared__ char sm[];
    uint32_t sb = smem_u32(sm);
    const GemmB gp = P.b[blockIdx.z];
    const int t = threadIdx.x, lane = t & 31, wid = t >> 5;
    const int row0 = blockIdx.y * 128, col0 = blockIdx.x * 128;

    const bf16* gA0 = gp.Ah + (size_t)row0 * lda;
    const bf16* gA1 = gp.Al + (size_t)row0 * lda;
    const bf16* gB0 = gp.Bh + (size_t)col0 * ldb;
    const bf16* gB1 = gp.Bl + (size_t)col0 * ldb;

    const int r_ld = t >> 3, kc = t & 7;   // 32 rows x 8 16B-chunks per pass

    auto issue = [&](int s) {
        int k0 = s * BKG;
        uint32_t dst = sb + (s % NSTAGE) * STAGE_B + kc * 16;
        const bf16* a0 = gA0 + k0 + kc * 8;
        const bf16* a1 = gA1 + k0 + kc * 8;
        const bf16* b0 = gB0 + k0 + kc * 8;
        const bf16* b1 = gB1 + k0 + kc * 8;
#pragma unroll
        for (int j = 0; j < 4; j++) {
            int r = r_ld + 32 * j;
            cp16(dst + r * RSB, a0 + (size_t)r * lda);
            cp16(dst + TILE_B + r * RSB, a1 + (size_t)r * lda);
            cp16(dst + 2 * TILE_B + r * RSB, b0 + (size_t)r * ldb);
            cp16(dst + 3 * TILE_B + r * RSB, b1 + (size_t)r * ldb);
        }
        cp_commit();
    };

    const int wm = wid & 1, wn = wid >> 1;
    float acc[4][4][4];
#pragma unroll
    for (int i = 0; i < 4; i++)
#pragma unroll
        for (int j = 0; j < 4; j++)
#pragma unroll
            for (int r = 0; r < 4; r++) acc[i][j][r] = 0.0f;

    const int arow = wm * 64 + (lane & 15);
    const int acolh = (lane >> 4) * 16;
    const int brow = wn * 32 + (lane & 7) + ((lane >> 4) << 3);
    const int bcolh = ((lane >> 3) & 1) * 16;

    const int S = K / BKG;
    issue(0);
    issue(1);
    for (int s = 0; s < S; s++) {
        if (s + 1 < S) cp_wait<1>(); else cp_wait<0>();
        __syncthreads();
        if (s + 2 < S) issue(s + 2);

        uint32_t st = sb + (s % NSTAGE) * STAGE_B;
        uint32_t aAh = st, aAl = st + TILE_B;
        uint32_t aBh = st + 2 * TILE_B, aBl = st + 3 * TILE_B;
#pragma unroll
        for (int kb = 0; kb < 4; kb++) {
            uint32_t ah[4][4], al[4][4], bh[4][2], bl[4][2];
#pragma unroll
            for (int mi = 0; mi < 4; mi++) {
                uint32_t off = (uint32_t)(arow + mi * 16) * RSB + kb * 32 + acolh;
                ldm4(aAh + off, ah[mi][0], ah[mi][1], ah[mi][2], ah[mi][3]);
                ldm4(aAl + off, al[mi][0], al[mi][1], al[mi][2], al[mi][3]);
            }
#pragma unroll
            for (int jp = 0; jp < 2; jp++) {
                uint32_t off = (uint32_t)(brow + jp * 16) * RSB + kb * 32 + bcolh;
                uint32_t r0, r1, r2, r3;
                ldm4(aBh + off, r0, r1, r2, r3);
                bh[jp * 2][0] = r0; bh[jp * 2][1] = r1;
                bh[jp * 2 + 1][0] = r2; bh[jp * 2 + 1][1] = r3;
                ldm4(aBl + off, r0, r1, r2, r3);
                bl[jp * 2][0] = r0; bl[jp * 2][1] = r1;
                bl[jp * 2 + 1][0] = r2; bl[jp * 2 + 1][1] = r3;
            }
#pragma unroll
            for (int mi = 0; mi < 4; mi++)
#pragma unroll
                for (int nj = 0; nj < 4; nj++) {
                    mma16816(acc[mi][nj], ah[mi], bh[nj]);
                    mma16816(acc[mi][nj], ah[mi], bl[nj]);
                    mma16816(acc[mi][nj], al[mi], bh[nj]);
                }
        }
    }

    // epilogue
    const int grow = lane >> 2, gc2 = (lane & 3) * 2;
#pragma unroll
    for (int mi = 0; mi < 4; mi++) {
#pragma unroll
        for (int nj = 0; nj < 4; nj++) {
            int col = col0 + wn * 32 + nj * 8 + gc2;
#pragma unroll
            for (int h = 0; h < 2; h++) {
                size_t row = (size_t)(row0 + wm * 64 + mi * 16 + grow + h * 8);
                float v0 = acc[mi][nj][h * 2], v1 = acc[mi][nj][h * 2 + 1];
                if (EPI == 1) { v0 = siluf(v0); v1 = siluf(v1); }
                if (WF32)
                    *(float2*)&gp.C[row * (size_t)N + col] = make_float2(v0, v1);
                if (WBF) {
                    bf16 h0, l0, h1, l1;
                    split1(v0, h0, l0);
                    split1(v1, h1, l1);
                    *(unsigned*)&gp.Ch[row * (size_t)N + col] = packu(h0, h1);
                    *(unsigned*)&gp.Cl[row * (size_t)N + col] = packu(l0, l1);
                }
            }
        }
    }
}

// ===================== conversion / elementwise kernels ====================

__global__ void conv_kernel(const float4* __restrict__ src,
                            bf16* __restrict__ hi, bf16* __restrict__ lo)
{
    int i = blockIdx.x * 256 + threadIdx.x;
    float4 v = src[i];
    bf16 h0, l0, h1, l1, h2, l2, h3, l3;
    split1(v.x, h0, l0); split1(v.y, h1, l1);
    split1(v.z, h2, l2); split1(v.w, h3, l3);
    ((uint2*)hi)[i] = make_uint2(packu(h0, h1), packu(h2, h3));
    ((uint2*)lo)[i] = make_uint2(packu(l0, l1), packu(l2, l3));
}

// z-batched conv of 3 equal-size fp32 arrays
struct Conv3 { const float4* s; bf16* h; bf16* l; };
struct Conv3P { Conv3 c[3]; };
__global__ void conv3_kernel(Conv3P P)
{
    Conv3 q = P.c[blockIdx.z];
    int i = blockIdx.x * 256 + threadIdx.x;
    float4 v = q.s[i];
    bf16 h0, l0, h1, l1, h2, l2, h3, l3;
    split1(v.x, h0, l0); split1(v.y, h1, l1);
    split1(v.z, h2, l2); split1(v.w, h3, l3);
    ((uint2*)q.h)[i] = make_uint2(packu(h0, h1), packu(h2, h3));
    ((uint2*)q.l)[i] = make_uint2(packu(l0, l1), packu(l2, l3));
}

// transpose + convert: src fp32 [R][C] -> dst hi/lo bf16 [C][R]
__global__ void trans_conv_kernel(const float* __restrict__ src,
                                  bf16* __restrict__ dhi, bf16* __restrict__ dlo,
                                  int R, int C)
{
    __shared__ float tile[32][33];
    int tx = threadIdx.x, ty = threadIdx.y;   // 16 x 8
    int r0 = blockIdx.y * 32, c0 = blockIdx.x * 32;
#pragma unroll
    for (int i = 0; i < 4; i++) {
        int r = ty + i * 8;
        float2 v = *(const float2*)&src[(size_t)(r0 + r) * C + c0 + tx * 2];
        tile[r][tx * 2] = v.x;
        tile[r][tx * 2 + 1] = v.y;
    }
    __syncthreads();
#pragma unroll
    for (int i = 0; i < 4; i++) {
        int c = ty + i * 8;
        float v0 = tile[tx * 2][c], v1 = tile[tx * 2 + 1][c];
        bf16 h0, l0, h1, l1;
        split1(v0, h0, l0); split1(v1, h1, l1);
        size_t o = (size_t)(c0 + c) * R + r0 + tx * 2;
        *(unsigned*)&dhi[o] = packu(h0, h1);
        *(unsigned*)&dlo[o] = packu(l0, l1);
    }
}

// bf16 hi/lo pair transpose: src [R][C] -> dst [C][R]
__global__ void trans2_bf16_kernel(const bf16* __restrict__ sh,
                                   const bf16* __restrict__ sl,
                                   bf16* __restrict__ dh_, bf16* __restrict__ dl_,
                                   int R, int C)
{
    __shared__ bf16 tile[32][34];
    int tx = threadIdx.x, ty = threadIdx.y;   // 16 x 8
    int r0 = blockIdx.y * 32, c0 = blockIdx.x * 32;
#pragma unroll
    for (int i = 0; i < 4; i++) {
        int r = ty + i * 8;
        unsigned v = *(const unsigned*)&sh[(size_t)(r0 + r) * C + c0 + tx * 2];
        tile[r][tx * 2] = ((bf16*)&v)[0];
        tile[r][tx * 2 + 1] = ((bf16*)&v)[1];
    }
    __syncthreads();
#pragma unroll
    for (int i = 0; i < 4; i++) {
        int c = ty + i * 8;
        *(unsigned*)&dh_[(size_t)(c0 + c) * R + r0 + tx * 2] =
            packu(tile[tx * 2][c], tile[tx * 2 + 1][c]);
    }
    __syncthreads();
#pragma unroll
    for (int i = 0; i < 4; i++) {
        int r = ty + i * 8;
        unsigned v = *(const unsigned*)&sl[(size_t)(r0 + r) * C + c0 + tx * 2];
        tile[r][tx * 2] = ((bf16*)&v)[0];
        tile[r][tx * 2 + 1] = ((bf16*)&v)[1];
    }
    __syncthreads();
#pragma unroll
    for (int i = 0; i < 4; i++) {
        int c = ty + i * 8;
        *(unsigned*)&dl_[(size_t)(c0 + c) * R + r0 + tx * 2] =
            packu(tile[tx * 2][c], tile[tx * 2 + 1][c]);
    }
}

// ak = silu(hk) -> bf16 hi/lo (row-major only)
__global__ void silu_conv_kernel(const float4* __restrict__ src,
                                 bf16* __restrict__ hi, bf16* __restrict__ lo)
{
    int i = blockIdx.x * 256 + threadIdx.x;
    float4 v = src[i];
    v.x = siluf(v.x); v.y = siluf(v.y); v.z = siluf(v.z); v.w = siluf(v.w);
    bf16 h0, l0, h1, l1, h2, l2, h3, l3;
    split1(v.x, h0, l0); split1(v.y, h1, l1);
    split1(v.z, h2, l2); split1(v.w, h3, l3);
    ((uint2*)hi)[i] = make_uint2(packu(h0, h1), packu(h2, h3));
    ((uint2*)lo)[i] = make_uint2(packu(l0, l1), packu(l2, l3));
}

// dp = 2*(pred - values)/(NTOK*DDIM) -> bf16 hi/lo (row-major only)
__global__ void dpred_conv_kernel(const float4* __restrict__ pred,
                                  const float4* __restrict__ vals,
                                  bf16* __restrict__ hi, bf16* __restrict__ lo)
{
    const float c = 2.0f / (float)((size_t)NTOK * DDIM);
    int i = blockIdx.x * 256 + threadIdx.x;
    float4 p = pred[i], v = vals[i];
    p.x = (p.x - v.x) * c; p.y = (p.y - v.y) * c;
    p.z = (p.z - v.z) * c; p.w = (p.w - v.w) * c;
    bf16 h0, l0, h1, l1, h2, l2, h3, l3;
    split1(p.x, h0, l0); split1(p.y, h1, l1);
    split1(p.z, h2, l2); split1(p.w, h3, l3);
    ((uint2*)hi)[i] = make_uint2(packu(h0, h1), packu(h2, h3));
    ((uint2*)lo)[i] = make_uint2(packu(l0, l1), packu(l2, l3));
}

// fused: dh = da * silu'(hk); write only DHT hi/lo (transposed)
__global__ void dh_trans_kernel(const float* __restrict__ da,
                                const float* __restrict__ hk,
                                bf16* __restrict__ thi, bf16* __restrict__ tlo,
                                int R, int C)
{
    __shared__ float tile[32][33];
    int tx = threadIdx.x, ty = threadIdx.y;   // 16 x 8
    int r0 = blockIdx.y * 32, c0 = blockIdx.x * 32;
#pragma unroll
    for (int i = 0; i < 4; i++) {
        int r = ty + i * 8;
        size_t o = (size_t)(r0 + r) * C + c0 + tx * 2;
        float2 d = *(const float2*)&da[o];
        float2 h = *(const float2*)&hk[o];
        float s;
        s = sigf(h.x); d.x *= s * (1.0f + h.x * (1.0f - s));
        s = sigf(h.y); d.y *= s * (1.0f + h.y * (1.0f - s));
        tile[r][tx * 2] = d.x;
        tile[r][tx * 2 + 1] = d.y;
    }
    __syncthreads();
#pragma unroll
    for (int i = 0; i < 4; i++) {
        int c = ty + i * 8;
        float v0 = tile[tx * 2][c], v1 = tile[tx * 2 + 1][c];
        bf16 h0, l0, h1, l1;
        split1(v0, h0, l0); split1(v1, h1, l1);
        size_t o = (size_t)(c0 + c) * R + r0 + tx * 2;
        *(unsigned*)&thi[o] = packu(h0, h1);
        *(unsigned*)&tlo[o] = packu(l0, l1);
    }
}

template <bool WF32>
__global__ void l2norm_kernel(float* __restrict__ x,
                              bf16* __restrict__ hi, bf16* __restrict__ lo)
{
    float4* p = (float4*)(x + (size_t)blockIdx.x * DDIM);
    int t = threadIdx.x;
    float4 v = p[t];
    float ss = v.x * v.x + v.y * v.y + v.z * v.z + v.w * v.w;
    __shared__ float red[8];
#pragma unroll
    for (int o = 16; o; o >>= 1) ss += __shfl_xor_sync(~0u, ss, o);
    if ((t & 31) == 0) red[t >> 5] = ss;
    __syncthreads();
    if (t < 8) {
        float s2 = red[t];
#pragma unroll
        for (int o = 4; o; o >>= 1) s2 += __shfl_xor_sync(0xffu, s2, o);
        if (t == 0) red[0] = s2;
    }
    __syncthreads();
    float scale = 1.0f / fmaxf(sqrtf(red[0]), 1e-12f);
    v.x *= scale; v.y *= scale; v.z *= scale; v.w *= scale;
    if (WF32) p[t] = v;
    size_t i = (size_t)blockIdx.x * 256 + t;
    bf16 h0, l0, h1, l1, h2, l2, h3, l3;
    split1(v.x, h0, l0); split1(v.y, h1, l1);
    split1(v.z, h2, l2); split1(v.w, h3, l3);
    ((uint2*)hi)[i] = make_uint2(packu(h0, h1), packu(h2, h3));
    ((uint2*)lo)[i] = make_uint2(packu(l0, l1), packu(l2, l3));
}

// x partial mean: grid (16, 8). xpart[sy][idx] = sum over 256 S entries.
__global__ void xmean_part_kernel(const float* __restrict__ x, float* __restrict__ xp)
{
    int idx = blockIdx.x * 256 + threadIdx.x;   // 0..4095 (b*1024+d)
    int sy = blockIdx.y;
    int b = idx >> 10, d = idx & 1023;
    const float* p = x + ((size_t)b * 2048 + sy * 256) * DDIM + d;
    float s = 0.0f;
#pragma unroll 8
    for (int ss = 0; ss < 256; ss++) s += p[(size_t)ss * DDIM];
    xp[sy * 4096 + idx] = s;
}

__global__ void xmean_fin_kernel(const float* __restrict__ xp, float* __restrict__ xm)
{
    int idx = blockIdx.x * 256 + threadIdx.x;
    float s = 0.0f;
#pragma unroll
    for (int j = 0; j < 8; j++) s += xp[j * 4096 + idx];
    xm[idx] = s * (1.0f / 2048.0f);
}

// warp-per-(gate, j): part[g*1024+j] = sum_b sigmoid(xm[b].W[j] + bias[j])
__global__ void gate_partial_kernel(
    const float* __restrict__ xm,
    const float* __restrict__ gdw, const float* __restrict__ gdb,
    const float* __restrict__ glw, const float* __restrict__ glb,
    const float* __restrict__ gmw, const float* __restrict__ gmb,
    float* __restrict__ part)
{
    int w = (blockIdx.x * 256 + threadIdx.x) >> 5;   // 0..3071
    int lane = threadIdx.x & 31;
    int g = w >> 10, j = w & 1023;
    const float* W = (g == 0) ? gdw : (g == 1) ? glw : gmw;
    const float* bias = (g == 0) ? gdb : (g == 1) ? glb : gmb;
    const float4* wr = (const float4*)(W + (size_t)j * DDIM);
    float bj = bias[j];
    float acc = 0.0f;
#pragma unroll
    for (int b = 0; b < 4; b++) {
        const float4* xr = (const float4*)(xm + b * DDIM);
        float s = 0.0f;
#pragma unroll
        for (int i = 0; i < 8; i++) {
            float4 a = xr[lane + 32 * i];
            float4 ww = wr[lane + 32 * i];
            s += a.x * ww.x + a.y * ww.y + a.z * ww.z + a.w * ww.w;
        }
#pragma unroll
        for (int o = 16; o; o >>= 1) s += __shfl_xor_sync(~0u, s, o);
        if (lane == 0) acc += sigf(s + bj);
    }
    if (lane == 0) part[g * 1024 + j] = acc;
}

// gates[g] = mean over 4*1024. grid 3 blocks x 256 threads.
__global__ void gate_final_kernel(const float* __restrict__ part, float* __restrict__ gates)
{
    int g = blockIdx.x, t = threadIdx.x;
    float v = part[g * 1024 + t] + part[g * 1024 + 256 + t]
            + part[g * 1024 + 512 + t] + part[g * 1024 + 768 + t];
    __shared__ float red[8];
#pragma unroll
    for (int o = 16; o; o >>= 1) v += __shfl_xor_sync(~0u, v, o);
    if ((t & 31) == 0) red[t >> 5] = v;
    __syncthreads();
    if (t < 8) {
        float s2 = red[t];
#pragma unroll
        for (int o = 4; o; o >>= 1) s2 += __shfl_xor_sync(0xffu, s2, o);
        if (t == 0) gates[g] = s2 * (1.0f / 4096.0f);
    }
}

__global__ void update_kernel(
    const float4* __restrict__ w0, const float4* __restrict__ w1,
    const float4* __restrict__ m0, const float4* __restrict__ m1,
    const float4* __restrict__ gg0, const float4* __restrict__ gg0b,
    const float4* __restrict__ gg1, const float4* __restrict__ gg1b,
    const float* __restrict__ gates, float4* __restrict__ out4)
{
    const int HD4 = HDIM * DDIM / 4;
    int i = blockIdx.x * 256 + threadIdx.x;
    float alpha = gates[0], theta = gates[1], eta = gates[2];
    float oma = 1.0f - alpha;
    if (i < HD4) {
        float4 ga = gg0[i], gb = gg0b[i], m = m0[i], w = w0[i], nm, nw;
        nm.x = eta * m.x - theta * (ga.x + gb.x); nw.x = oma * w.x + nm.x;
        nm.y = eta * m.y - theta * (ga.y + gb.y); nw.y = oma * w.y + nm.y;
        nm.z = eta * m.z - theta * (ga.z + gb.z); nw.z = oma * w.z + nm.z;
        nm.w = eta * m.w - theta * (ga.w + gb.w); nw.w = oma * w.w + nm.w;
        out4[2097152 + i] = nw;
        out4[3145728 + i] = nm;
    } else {
        int j = i - HD4;
        float4 ga = gg1[j], gb = gg1b[j], m = m1[j], w = w1[j], nm, nw;
        nm.x = eta * m.x - theta * (ga.x + gb.x); nw.x = oma * w.x + nm.x;
        nm.y = eta * m.y - theta * (ga.y + gb.y); nw.y = oma * w.y + nm.y;
        nm.z = eta * m.z - theta * (ga.z + gb.z); nw.z = oma * w.z + nm.z;
        nm.w = eta * m.w - theta * (ga.w + gb.w); nw.w = oma * w.w + nm.w;
        out4[2621440 + j] = nw;
        out4[3670016 + j] = nm;
    }
}

// ===================== host ================================================

static GemmB3 mk1(const bf16* Ah, const bf16* Al, const bf16* Bh, const bf16* Bl,
                  float* C, bf16* Ch, bf16* Cl)
{
    GemmB3 p{};
    p.b[0] = {Ah, Al, Bh, Bl, C, Ch, Cl};
    return p;
}

extern "C" void kernel_launch(void* const* d_in, const int* in_sizes, int n_in,
                              void* d_out, int out_size)
{
    (void)in_sizes; (void)n_in; (void)out_size;
    const float* x      = (const float*)d_in[0];
    const float* kp_w1  = (const float*)d_in[1];
    const float* kp_w2  = (const float*)d_in[2];
    const float* vp_w1  = (const float*)d_in[3];
    const float* vp_w2  = (const float*)d_in[4];
    const float* qp_w1  = (const float*)d_in[5];
    const float* qp_w2  = (const float*)d_in[6];
    const float* gd_w   = (const float*)d_in[7];
    const float* gd_b   = (const float*)d_in[8];
    const float* gl_w   = (const float*)d_in[9];
    const float* gl_b   = (const float*)d_in[10];
    const float* gm_w   = (const float*)d_in[11];
    const float* gm_b   = (const float*)d_in[12];
    const float* mem_w0 = (const float*)d_in[13];
    const float* mem_w1 = (const float*)d_in[14];
    const float* mom0   = (const float*)d_in[15];
    const float* mom1   = (const float*)d_in[16];
    const float* out_w  = (const float*)d_in[17];
    float* out = (float*)d_out;

    float *keys, *values, *queries, *hk, *pred, *da, *gg0, *gg0b, *gg1, *gg1b;
    float *xpart, *xmean, *gpart, *gates;
    bf16 *bh, *bl;
    cudaGetSymbolAddress((void**)&keys, g_keys);
    cudaGetSymbolAddress((void**)&values, g_values);
    cudaGetSymbolAddress((void**)&queries, g_queries);
    cudaGetSymbolAddress((void**)&hk, g_hk);
    cudaGetSymbolAddress((void**)&pred, g_pred);
    cudaGetSymbolAddress((void**)&da, g_da);
    cudaGetSymbolAddress((void**)&gg0, g_g0);
    cudaGetSymbolAddress((void**)&gg0b, g_g0b);
    cudaGetSymbolAddress((void**)&gg1, g_g1);
    cudaGetSymbolAddress((void**)&gg1b, g_g1b);
    cudaGetSymbolAddress((void**)&xpart, g_xpart);
    cudaGetSymbolAddress((void**)&xmean, g_xmean);
    cudaGetSymbolAddress((void**)&gpart, g_gpart);
    cudaGetSymbolAddress((void**)&gates, g_gates);
    cudaGetSymbolAddress((void**)&bh, g_bfh);
    cudaGetSymbolAddress((void**)&bl, g_bfl);

    cudaFuncSetAttribute(mma_gemm<1, false, true>, cudaFuncAttributeMaxDynamicSharedMemorySize, GSMEM);
    cudaFuncSetAttribute(mma_gemm<1, true, false>, cudaFuncAttributeMaxDynamicSharedMemorySize, GSMEM);
    cudaFuncSetAttribute(mma_gemm<0, false, true>, cudaFuncAttributeMaxDynamicSharedMemorySize, GSMEM);
    cudaFuncSetAttribute(mma_gemm<0, true, false>, cudaFuncAttributeMaxDynamicSharedMemorySize, GSMEM);

    // one-time stream/event resources (no device-memory allocation)
    static cudaStream_t s1 = nullptr;
    static cudaEvent_t evRoot, evW1, evW2, evWM, evW1T, evG, evKQ, evKT, evAK,
        evDP, evG1, evEnd;
    if (s1 == nullptr) {
        cudaStreamCreateWithFlags(&s1, cudaStreamNonBlocking);
        cudaEventCreateWithFlags(&evRoot, cudaEventDisableTiming);
        cudaEventCreateWithFlags(&evW1, cudaEventDisableTiming);
        cudaEventCreateWithFlags(&evW2, cudaEventDisableTiming);
        cudaEventCreateWithFlags(&evWM, cudaEventDisableTiming);
        cudaEventCreateWithFlags(&evW1T, cudaEventDisableTiming);
        cudaEventCreateWithFlags(&evG, cudaEventDisableTiming);
        cudaEventCreateWithFlags(&evKQ, cudaEventDisableTiming);
        cudaEventCreateWithFlags(&evKT, cudaEventDisableTiming);
        cudaEventCreateWithFlags(&evAK, cudaEventDisableTiming);
        cudaEventCreateWithFlags(&evDP, cudaEventDisableTiming);
        cudaEventCreateWithFlags(&evG1, cudaEventDisableTiming);
        cudaEventCreateWithFlags(&evEnd, cudaEventDisableTiming);
    }

    dim3 blk(256);
    dim3 ttb(16, 8);

    // ---- fork side stream off the capture-origin (default) stream ----
    cudaEventRecord(evRoot, 0);
    cudaStreamWaitEvent(s1, evRoot, 0);

    // stream0: x conversion
    conv_kernel<<<8192, 256>>>((const float4*)x, bh + O_X, bl + O_X);

    // s1: weight conversions + gates
    {
        Conv3P p{};
        p.c[0] = {(const float4*)kp_w1, bh + O_KP1, bl + O_KP1};
        p.c[1] = {(const float4*)vp_w1, bh + O_VP1, bl + O_VP1};
        p.c[2] = {(const float4*)qp_w1, bh + O_QP1, bl + O_QP1};
        conv3_kernel<<<dim3(1024, 1, 3), 256, 0, s1>>>(p);
    }
    cudaEventRecord(evW1, s1);
    xmean_part_kernel<<<dim3(16, 8), 256, 0, s1>>>(x, xpart);
    xmean_fin_kernel<<<16, 256, 0, s1>>>(xpart, xmean);
    gate_partial_kernel<<<384, 256, 0, s1>>>(xmean, gd_w, gd_b, gl_w, gl_b,
                                             gm_w, gm_b, gpart);

    // stream0: projections layer 1 (z=3)
    cudaStreamWaitEvent(0, evW1, 0);
    {
        GemmB3 p{};
        p.b[0] = {bh + O_X, bl + O_X, bh + O_KP1, bl + O_KP1, nullptr, bh + O_T1, bl + O_T1};
        p.b[1] = {bh + O_X, bl + O_X, bh + O_VP1, bl + O_VP1, nullptr, bh + O_T1B, bl + O_T1B};
        p.b[2] = {bh + O_X, bl + O_X, bh + O_QP1, bl + O_QP1, nullptr, bh + O_T1C, bl + O_T1C};
        mma_gemm<1, false, true><<<dim3(8, 64, 3), blk, GSMEM>>>(p, NTOK, DDIM, DDIM, DDIM, DDIM);
    }

    // s1: rest of gates + remaining conversions
    gate_final_kernel<<<3, 256, 0, s1>>>(gpart, gates);
    cudaEventRecord(evG, s1);
    {
        Conv3P p{};
        p.c[0] = {(const float4*)kp_w2, bh + O_KP2, bl + O_KP2};
        p.c[1] = {(const float4*)vp_w2, bh + O_VP2, bl + O_VP2};
        p.c[2] = {(const float4*)qp_w2, bh + O_QP2, bl + O_QP2};
        conv3_kernel<<<dim3(1024, 1, 3), 256, 0, s1>>>(p);
    }
    cudaEventRecord(evW2, s1);
    conv_kernel<<<2048, 256, 0, s1>>>((const float4*)mem_w0, bh + O_M0, bl + O_M0);
    conv_kernel<<<2048, 256, 0, s1>>>((const float4*)mem_w1, bh + O_M1, bl + O_M1);
    conv_kernel<<<1024, 256, 0, s1>>>((const float4*)out_w, bh + O_OW, bl + O_OW);
    cudaEventRecord(evWM, s1);
    trans_conv_kernel<<<dim3(HDIM / 32, DDIM / 32), ttb, 0, s1>>>(
        mem_w1, bh + O_M1T, bl + O_M1T, DDIM, HDIM);   // w1T [H][D]
    cudaEventRecord(evW1T, s1);

    // s1: W' = out_w @ mem_w1  ([D][H], K=D); out = aq @ W'^T later
    mma_gemm<0, false, true><<<dim3(16, 8, 1), blk, GSMEM, s1>>>(
        mk1(bh + O_OW, bl + O_OW, bh + O_M1T, bl + O_M1T,
            nullptr, bh + O_WP, bl + O_WP),
        DDIM, HDIM, DDIM, DDIM, DDIM);

    // stream0: projections layer 2 (z=3), l2norms
    cudaStreamWaitEvent(0, evW2, 0);
    {
        GemmB3 p{};
        p.b[0] = {bh + O_T1, bl + O_T1, bh + O_KP2, bl + O_KP2, keys, nullptr, nullptr};
        p.b[1] = {bh + O_T1B, bl + O_T1B, bh + O_VP2, bl + O_VP2, values, nullptr, nullptr};
        p.b[2] = {bh + O_T1C, bl + O_T1C, bh + O_QP2, bl + O_QP2, queries, nullptr, nullptr};
        mma_gemm<1, true, false><<<dim3(8, 64, 3), blk, GSMEM>>>(p, NTOK, DDIM, DDIM, DDIM, DDIM);
    }
    l2norm_kernel<false><<<NTOK, 256>>>(keys, bh + O_KEY, bl + O_KEY);
    l2norm_kernel<false><<<NTOK, 256>>>(queries, bh + O_Q, bl + O_Q);
    cudaEventRecord(evKQ, 0);

    // s1: keysT (bf16 transpose) + q-chain (aq -> out via W')
    cudaStreamWaitEvent(s1, evKQ, 0);
    trans2_bf16_kernel<<<dim3(DDIM / 32, NTOK / 32), ttb, 0, s1>>>(
        bh + O_KEY, bl + O_KEY, bh + O_KEYT, bl + O_KEYT, NTOK, DDIM);
    cudaEventRecord(evKT, s1);
    mma_gemm<1, false, true><<<dim3(16, 64, 1), blk, GSMEM, s1>>>(
        mk1(bh + O_Q, bl + O_Q, bh + O_M0, bl + O_M0, nullptr, bh + O_AQ, bl + O_AQ),
        NTOK, HDIM, DDIM, DDIM, DDIM);
    mma_gemm<0, true, false><<<dim3(8, 64, 1), blk, GSMEM, s1>>>(
        mk1(bh + O_AQ, bl + O_AQ, bh + O_WP, bl + O_WP, out, nullptr, nullptr),
        NTOK, DDIM, HDIM, HDIM, HDIM);

    // stream0: loss forward on keys
    cudaStreamWaitEvent(0, evWM, 0);
    mma_gemm<0, true, false><<<dim3(16, 64, 1), blk, GSMEM>>>(
        mk1(bh + O_KEY, bl + O_KEY, bh + O_M0, bl + O_M0, hk, nullptr, nullptr),
        NTOK, HDIM, DDIM, DDIM, DDIM);
    silu_conv_kernel<<<NTOK * HDIM / 1024, 256>>>(
        (const float4*)hk, bh + O_AK, bl + O_AK);
    cudaEventRecord(evAK, 0);
    mma_gemm<0, true, false><<<dim3(8, 64, 1), blk, GSMEM>>>(
        mk1(bh + O_AK, bl + O_AK, bh + O_M1, bl + O_M1, pred, nullptr, nullptr),
        NTOK, DDIM, HDIM, HDIM, HDIM);
    dpred_conv_kernel<<<NTOK * DDIM / 1024, 256>>>(
        (const float4*)pred, (const float4*)values, bh + O_DP, bl + O_DP);
    cudaEventRecord(evDP, 0);

    // s1 (after q-chain): AKT + DPT transposes, then g1 (split-K 2 via z)
    cudaStreamWaitEvent(s1, evAK, 0);
    trans2_bf16_kernel<<<dim3(HDIM / 32, NTOK / 32), ttb, 0, s1>>>(
        bh + O_AK, bl + O_AK, bh + O_AKT, bl + O_AKT, NTOK, HDIM);
    cudaStreamWaitEvent(s1, evDP, 0);
    trans2_bf16_kernel<<<dim3(DDIM / 32, NTOK / 32), ttb, 0, s1>>>(
        bh + O_DP, bl + O_DP, bh + O_DPT, bl + O_DPT, NTOK, DDIM);
    {
        GemmB3 p{};
        p.b[0] = {bh + O_DPT, bl + O_DPT, bh + O_AKT, bl + O_AKT, gg1, nullptr, nullptr};
        p.b[1] = {bh + O_DPT + NTOK / 2, bl + O_DPT + NTOK / 2,
                  bh + O_AKT + NTOK / 2, bl + O_AKT + NTOK / 2, gg1b, nullptr, nullptr};
        mma_gemm<0, true, false><<<dim3(16, 8, 2), blk, GSMEM, s1>>>(
            p, DDIM, HDIM, NTOK / 2, NTOK, NTOK);
    }
    cudaEventRecord(evG1, s1);
    cudaEventRecord(evEnd, s1);

    // stream0: da[N,H] = dpred . w1T  (K = D)
    cudaStreamWaitEvent(0, evW1T, 0);
    mma_gemm<0, true, false><<<dim3(16, 64, 1), blk, GSMEM>>>(
        mk1(bh + O_DP, bl + O_DP, bh + O_M1T, bl + O_M1T, da, nullptr, nullptr),
        NTOK, HDIM, DDIM, DDIM, DDIM);
    dh_trans_kernel<<<dim3(HDIM / 32, NTOK / 32), ttb>>>(
        da, hk, bh + O_DHT, bl + O_DHT, NTOK, HDIM);
    // g0[H,D] = dhT . keysT    (K = NTOK, split-K 2 via z)
    cudaStreamWaitEvent(0, evKT, 0);
    {
        GemmB3 p{};
        p.b[0] = {bh + O_DHT, bl + O_DHT, bh + O_KEYT, bl + O_KEYT, gg0, nullptr, nullptr};
        p.b[1] = {bh + O_DHT + NTOK / 2, bl + O_DHT + NTOK / 2,
                  bh + O_KEYT + NTOK / 2, bl + O_KEYT + NTOK / 2, gg0b, nullptr, nullptr};
        mma_gemm<0, true, false><<<dim3(8, 16, 2), blk, GSMEM>>>(
            p, HDIM, DDIM, NTOK / 2, NTOK, NTOK);
    }

    // ---- weight / momentum update (needs gates, g0, g1) ----
    cudaStreamWaitEvent(0, evG, 0);
    cudaStreamWaitEvent(0, evG1, 0);
    update_kernel<<<2 * HDIM * DDIM / 4 / 256, 256>>>(
        (const float4*)mem_w0, (const float4*)mem_w1,
        (const float4*)mom0, (const float4*)mom1,
        (const float4*)gg0, (const float4*)gg0b,
        (const float4*)gg1, (const float4*)gg1b, gates, (float4*)out);

    // ---- join side stream back into the origin stream ----
    cudaStreamWaitEvent(0, evEnd, 0);
}

// round 15
// speedup vs baseline: 1.0300x; 1.0038x over previous
#include <cuda_runtime.h>
#include <cuda_bf16.h>
#include <cstdint>

#define NTOK 8192
#define DDIM 1024
#define HDIM 2048
#define MI 1048576ULL

typedef __nv_bfloat16 bf16;

// ===================== scratch (static device globals) ======================
__device__ float g_keys[NTOK * DDIM];
__device__ float g_values[NTOK * DDIM];
__device__ float g_queries[NTOK * DDIM];
__device__ float g_hk[NTOK * HDIM];
__device__ float g_pred[NTOK * DDIM];
__device__ float g_da[NTOK * HDIM];
__device__ float g_g0[HDIM * DDIM];
__device__ float g_g0b[HDIM * DDIM];
__device__ float g_g1[DDIM * HDIM];
__device__ float g_g1b[DDIM * HDIM];
__device__ float g_xpart[8 * 4 * DDIM];
__device__ float g_xmean[4 * DDIM];
__device__ float g_gpart[3 * DDIM];
__device__ float g_gates[3];

__device__ bf16 g_bfh[157 * MI];
__device__ bf16 g_bfl[157 * MI];

// offsets (elements) inside g_bfh/g_bfl
#define O_X    (0 * MI)
#define O_T1   (8 * MI)
#define O_KEY  (16 * MI)
#define O_KEYT (24 * MI)
#define O_Q    (32 * MI)
#define O_AQ   (40 * MI)   // 16Mi
#define O_WP   (56 * MI)   // W' = out_w @ mem_w1, [D][H], 2Mi
#define O_AK   (64 * MI)   // 16Mi
#define O_AKT  (80 * MI)   // 16Mi
#define O_DP   (96 * MI)
#define O_DPT  (104 * MI)
#define O_DHT  (112 * MI)  // 16Mi
#define O_KP1  (128 * MI)
#define O_KP2  (129 * MI)
#define O_VP1  (130 * MI)
#define O_VP2  (131 * MI)
#define O_QP1  (132 * MI)
#define O_QP2  (133 * MI)
#define O_OW   (134 * MI)
#define O_M0   (135 * MI)  // 2Mi
#define O_M1   (137 * MI)  // 2Mi
#define O_M1T  (139 * MI)  // 2Mi
#define O_T1B  (141 * MI)  // 8Mi
#define O_T1C  (149 * MI)  // 8Mi

// ===================== small helpers =======================================
static __device__ __forceinline__ float sigf(float x) {
    return 1.0f / (1.0f + __expf(-x));
}
static __device__ __forceinline__ float siluf(float x) { return x * sigf(x); }

static __device__ __forceinline__ void split1(float v, bf16& h, bf16& l) {
    h = __float2bfloat16(v);
    l = __float2bfloat16(v - __bfloat162float(h));
}
static __device__ __forceinline__ unsigned packu(bf16 a, bf16 b) {
    unsigned short x = *(unsigned short*)&a, y = *(unsigned short*)&b;
    return (unsigned)x | ((unsigned)y << 16);
}
static __device__ __forceinline__ uint32_t smem_u32(const void* p) {
    uint32_t a;
    asm("{ .reg .u64 t; cvta.to.shared.u64 t, %1; cvt.u32.u64 %0, t; }"
        : "=r"(a) : "l"(p));
    return a;
}

// cp.async / ldmatrix / mma wrappers (sm_80-compatible)
static __device__ __forceinline__ void cp16(uint32_t s, const void* g) {
    asm volatile("cp.async.cg.shared.global [%0], [%1], 16;" :: "r"(s), "l"(g));
}
static __device__ __forceinline__ void cp_commit() {
    asm volatile("cp.async.commit_group;" ::: "memory");
}
template <int N>
static __device__ __forceinline__ void cp_wait() {
    asm volatile("cp.async.wait_group %0;" :: "n"(N) : "memory");
}
static __device__ __forceinline__ void ldm4(uint32_t a, uint32_t& r0, uint32_t& r1,
                                            uint32_t& r2, uint32_t& r3) {
    asm volatile("ldmatrix.sync.aligned.m8n8.x4.shared.b16 {%0,%1,%2,%3}, [%4];"
                 : "=r"(r0), "=r"(r1), "=r"(r2), "=r"(r3) : "r"(a));
}
static __device__ __forceinline__ void mma16816(float* c, const uint32_t* a,
                                                const uint32_t* b) {
    asm volatile(
        "mma.sync.aligned.m16n8k16.row.col.f32.bf16.bf16.f32 "
        "{%0,%1,%2,%3}, {%4,%5,%6,%7}, {%8,%9}, {%0,%1,%2,%3};"
        : "+f"(c[0]), "+f"(c[1]), "+f"(c[2]), "+f"(c[3])
        : "r"(a[0]), "r"(a[1]), "r"(a[2]), "r"(a[3]), "r"(b[0]), "r"(b[1]));
}

// ===================== batched mma.sync GEMM ===============================
// Per z-slice: C[M,N] = sum_k A[m,k]*B[n,k]; A/B bf16 hi+lo rows with leading
// dims lda/ldb. CTA tile 128x128x64, 8 warps (64x32), bf16x3, 3-stage
// cp.async, single __syncthreads per stage. (R7-proven best config.)
#define BKG 64
#define RSB 144                       // 64 bf16 (128B) + 16B pad
#define TILE_B (128 * RSB)            // 18432
#define STAGE_B (4 * TILE_B)          // 73728
#define NSTAGE 3
#define GSMEM (NSTAGE * STAGE_B)      // 221184

struct GemmB {
    const bf16 *Ah, *Al, *Bh, *Bl;
    float* C;
    bf16 *Ch, *Cl;
};
struct GemmB3 { GemmB b[3]; };

template <int EPI, bool WF32, bool WBF>
__global__ __launch_bounds__(256, 1)
void mma_gemm(GemmB3 P, int M, int N, int K, int lda, int ldb)
{
    extern __shared__ char sm[];
    uint32_t sb = smem_u32(sm);
    const GemmB gp = P.b[blockIdx.z];
    const int t = threadIdx.x, lane = t & 31, wid = t >> 5;
    const int row0 = blockIdx.y * 128, col0 = blockIdx.x * 128;

    const bf16* gA0 = gp.Ah + (size_t)row0 * lda;
    const bf16* gA1 = gp.Al + (size_t)row0 * lda;
    const bf16* gB0 = gp.Bh + (size_t)col0 * ldb;
    const bf16* gB1 = gp.Bl + (size_t)col0 * ldb;

    const int r_ld = t >> 3, kc = t & 7;   // 32 rows x 8 16B-chunks per pass

    auto issue = [&](int s) {
        int k0 = s * BKG;
        uint32_t dst = sb + (s % NSTAGE) * STAGE_B + kc * 16;
        const bf16* a0 = gA0 + k0 + kc * 8;
        const bf16* a1 = gA1 + k0 + kc * 8;
        const bf16* b0 = gB0 + k0 + kc * 8;
        const bf16* b1 = gB1 + k0 + kc * 8;
#pragma unroll
        for (int j = 0; j < 4; j++) {
            int r = r_ld + 32 * j;
            cp16(dst + r * RSB, a0 + (size_t)r * lda);
            cp16(dst + TILE_B + r * RSB, a1 + (size_t)r * lda);
            cp16(dst + 2 * TILE_B + r * RSB, b0 + (size_t)r * ldb);
            cp16(dst + 3 * TILE_B + r * RSB, b1 + (size_t)r * ldb);
        }
        cp_commit();
    };

    const int wm = wid & 1, wn = wid >> 1;
    float acc[4][4][4];
#pragma unroll
    for (int i = 0; i < 4; i++)
#pragma unroll
        for (int j = 0; j < 4; j++)
#pragma unroll
            for (int r = 0; r < 4; r++) acc[i][j][r] = 0.0f;

    const int arow = wm * 64 + (lane & 15);
    const int acolh = (lane >> 4) * 16;
    const int brow = wn * 32 + (lane & 7) + ((lane >> 4) << 3);
    const int bcolh = ((lane >> 3) & 1) * 16;

    const int S = K / BKG;
    issue(0);
    issue(1);
    for (int s = 0; s < S; s++) {
        if (s + 1 < S) cp_wait<1>(); else cp_wait<0>();
        __syncthreads();
        if (s + 2 < S) issue(s + 2);

        uint32_t st = sb + (s % NSTAGE) * STAGE_B;
        uint32_t aAh = st, aAl = st + TILE_B;
        uint32_t aBh = st + 2 * TILE_B, aBl = st + 3 * TILE_B;
#pragma unroll
        for (int kb = 0; kb < 4; kb++) {
            uint32_t ah[4][4], al[4][4], bh[4][2], bl[4][2];
#pragma unroll
            for (int mi = 0; mi < 4; mi++) {
                uint32_t off = (uint32_t)(arow + mi * 16) * RSB + kb * 32 + acolh;
                ldm4(aAh + off, ah[mi][0], ah[mi][1], ah[mi][2], ah[mi][3]);
                ldm4(aAl + off, al[mi][0], al[mi][1], al[mi][2], al[mi][3]);
            }
#pragma unroll
            for (int jp = 0; jp < 2; jp++) {
                uint32_t off = (uint32_t)(brow + jp * 16) * RSB + kb * 32 + bcolh;
                uint32_t r0, r1, r2, r3;
                ldm4(aBh + off, r0, r1, r2, r3);
                bh[jp * 2][0] = r0; bh[jp * 2][1] = r1;
                bh[jp * 2 + 1][0] = r2; bh[jp * 2 + 1][1] = r3;
                ldm4(aBl + off, r0, r1, r2, r3);
                bl[jp * 2][0] = r0; bl[jp * 2][1] = r1;
                bl[jp * 2 + 1][0] = r2; bl[jp * 2 + 1][1] = r3;
            }
#pragma unroll
            for (int mi = 0; mi < 4; mi++)
#pragma unroll
                for (int nj = 0; nj < 4; nj++) {
                    mma16816(acc[mi][nj], ah[mi], bh[nj]);
                    mma16816(acc[mi][nj], ah[mi], bl[nj]);
                    mma16816(acc[mi][nj], al[mi], bh[nj]);
                }
        }
    }

    // epilogue
    const int grow = lane >> 2, gc2 = (lane & 3) * 2;
#pragma unroll
    for (int mi = 0; mi < 4; mi++) {
#pragma unroll
        for (int nj = 0; nj < 4; nj++) {
            int col = col0 + wn * 32 + nj * 8 + gc2;
#pragma unroll
            for (int h = 0; h < 2; h++) {
                size_t row = (size_t)(row0 + wm * 64 + mi * 16 + grow + h * 8);
                float v0 = acc[mi][nj][h * 2], v1 = acc[mi][nj][h * 2 + 1];
                if (EPI == 1) { v0 = siluf(v0); v1 = siluf(v1); }
                if (WF32)
                    *(float2*)&gp.C[row * (size_t)N + col] = make_float2(v0, v1);
                if (WBF) {
                    bf16 h0, l0, h1, l1;
                    split1(v0, h0, l0);
                    split1(v1, h1, l1);
                    *(unsigned*)&gp.Ch[row * (size_t)N + col] = packu(h0, h1);
                    *(unsigned*)&gp.Cl[row * (size_t)N + col] = packu(l0, l1);
                }
            }
        }
    }
}

// ===================== conversion / elementwise kernels ====================

__global__ void conv_kernel(const float4* __restrict__ src,
                            bf16* __restrict__ hi, bf16* __restrict__ lo)
{
    int i = blockIdx.x * 256 + threadIdx.x;
    float4 v = src[i];
    bf16 h0, l0, h1, l1, h2, l2, h3, l3;
    split1(v.x, h0, l0); split1(v.y, h1, l1);
    split1(v.z, h2, l2); split1(v.w, h3, l3);
    ((uint2*)hi)[i] = make_uint2(packu(h0, h1), packu(h2, h3));
    ((uint2*)lo)[i] = make_uint2(packu(l0, l1), packu(l2, l3));
}

// z-batched conv of 3 equal-size fp32 arrays
struct Conv3 { const float4* s; bf16* h; bf16* l; };
struct Conv3P { Conv3 c[3]; };
__global__ void conv3_kernel(Conv3P P)
{
    Conv3 q = P.c[blockIdx.z];
    int i = blockIdx.x * 256 + threadIdx.x;
    float4 v = q.s[i];
    bf16 h0, l0, h1, l1, h2, l2, h3, l3;
    split1(v.x, h0, l0); split1(v.y, h1, l1);
    split1(v.z, h2, l2); split1(v.w, h3, l3);
    ((uint2*)q.h)[i] = make_uint2(packu(h0, h1), packu(h2, h3));
    ((uint2*)q.l)[i] = make_uint2(packu(l0, l1), packu(l2, l3));
}

// transpose + convert: src fp32 [R][C] -> dst hi/lo bf16 [C][R]
__global__ void trans_conv_kernel(const float* __restrict__ src,
                                  bf16* __restrict__ dhi, bf16* __restrict__ dlo,
                                  int R, int C)
{
    __shared__ float tile[32][33];
    int tx = threadIdx.x, ty = threadIdx.y;   // 16 x 8
    int r0 = blockIdx.y * 32, c0 = blockIdx.x * 32;
#pragma unroll
    for (int i = 0; i < 4; i++) {
        int r = ty + i * 8;
        float2 v = *(const float2*)&src[(size_t)(r0 + r) * C + c0 + tx * 2];
        tile[r][tx * 2] = v.x;
        tile[r][tx * 2 + 1] = v.y;
    }
    __syncthreads();
#pragma unroll
    for (int i = 0; i < 4; i++) {
        int c = ty + i * 8;
        float v0 = tile[tx * 2][c], v1 = tile[tx * 2 + 1][c];
        bf16 h0, l0, h1, l1;
        split1(v0, h0, l0); split1(v1, h1, l1);
        size_t o = (size_t)(c0 + c) * R + r0 + tx * 2;
        *(unsigned*)&dhi[o] = packu(h0, h1);
        *(unsigned*)&dlo[o] = packu(l0, l1);
    }
}

// bf16 hi/lo pair transpose: src [R][C] -> dst [C][R]
__global__ void trans2_bf16_kernel(const bf16* __restrict__ sh,
                                   const bf16* __restrict__ sl,
                                   bf16* __restrict__ dh_, bf16* __restrict__ dl_,
                                   int R, int C)
{
    __shared__ bf16 tile[32][34];
    int tx = threadIdx.x, ty = threadIdx.y;   // 16 x 8
    int r0 = blockIdx.y * 32, c0 = blockIdx.x * 32;
#pragma unroll
    for (int i = 0; i < 4; i++) {
        int r = ty + i * 8;
        unsigned v = *(const unsigned*)&sh[(size_t)(r0 + r) * C + c0 + tx * 2];
        tile[r][tx * 2] = ((bf16*)&v)[0];
        tile[r][tx * 2 + 1] = ((bf16*)&v)[1];
    }
    __syncthreads();
#pragma unroll
    for (int i = 0; i < 4; i++) {
        int c = ty + i * 8;
        *(unsigned*)&dh_[(size_t)(c0 + c) * R + r0 + tx * 2] =
            packu(tile[tx * 2][c], tile[tx * 2 + 1][c]);
    }
    __syncthreads();
#pragma unroll
    for (int i = 0; i < 4; i++) {
        int r = ty + i * 8;
        unsigned v = *(const unsigned*)&sl[(size_t)(r0 + r) * C + c0 + tx * 2];
        tile[r][tx * 2] = ((bf16*)&v)[0];
        tile[r][tx * 2 + 1] = ((bf16*)&v)[1];
    }
    __syncthreads();
#pragma unroll
    for (int i = 0; i < 4; i++) {
        int c = ty + i * 8;
        *(unsigned*)&dl_[(size_t)(c0 + c) * R + r0 + tx * 2] =
            packu(tile[tx * 2][c], tile[tx * 2 + 1][c]);
    }
}

// fused: ak = silu(hk); write AK hi/lo + AKT hi/lo (transposed)
__global__ void silu_conv_trans_kernel(const float* __restrict__ src,
                                       bf16* __restrict__ hi, bf16* __restrict__ lo,
                                       bf16* __restrict__ thi, bf16* __restrict__ tlo,
                                       int R, int C)
{
    __shared__ float tile[32][33];
    int tx = threadIdx.x, ty = threadIdx.y;   // 16 x 8
    int r0 = blockIdx.y * 32, c0 = blockIdx.x * 32;
#pragma unroll
    for (int i = 0; i < 4; i++) {
        int r = ty + i * 8;
        size_t o = (size_t)(r0 + r) * C + c0 + tx * 2;
        float2 v = *(const float2*)&src[o];
        v.x = siluf(v.x); v.y = siluf(v.y);
        tile[r][tx * 2] = v.x;
        tile[r][tx * 2 + 1] = v.y;
        bf16 h0, l0, h1, l1;
        split1(v.x, h0, l0); split1(v.y, h1, l1);
        *(unsigned*)&hi[o] = packu(h0, h1);
        *(unsigned*)&lo[o] = packu(l0, l1);
    }
    __syncthreads();
#pragma unroll
    for (int i = 0; i < 4; i++) {
        int c = ty + i * 8;
        float v0 = tile[tx * 2][c], v1 = tile[tx * 2 + 1][c];
        bf16 h0, l0, h1, l1;
        split1(v0, h0, l0); split1(v1, h1, l1);
        size_t o = (size_t)(c0 + c) * R + r0 + tx * 2;
        *(unsigned*)&thi[o] = packu(h0, h1);
        *(unsigned*)&tlo[o] = packu(l0, l1);
    }
}

// fused: dp = 2*(pred - values)/(NTOK*DDIM); write DP hi/lo + DPT hi/lo
__global__ void dpred_conv_trans_kernel(const float* __restrict__ pred,
                                        const float* __restrict__ vals,
                                        bf16* __restrict__ hi, bf16* __restrict__ lo,
                                        bf16* __restrict__ thi, bf16* __restrict__ tlo,
                                        int R, int C)
{
    __shared__ float tile[32][33];
    const float cst = 2.0f / (float)((size_t)NTOK * DDIM);
    int tx = threadIdx.x, ty = threadIdx.y;   // 16 x 8
    int r0 = blockIdx.y * 32, c0 = blockIdx.x * 32;
#pragma unroll
    for (int i = 0; i < 4; i++) {
        int r = ty + i * 8;
        size_t o = (size_t)(r0 + r) * C + c0 + tx * 2;
        float2 p = *(const float2*)&pred[o];
        float2 v = *(const float2*)&vals[o];
        p.x = (p.x - v.x) * cst; p.y = (p.y - v.y) * cst;
        tile[r][tx * 2] = p.x;
        tile[r][tx * 2 + 1] = p.y;
        bf16 h0, l0, h1, l1;
        split1(p.x, h0, l0); split1(p.y, h1, l1);
        *(unsigned*)&hi[o] = packu(h0, h1);
        *(unsigned*)&lo[o] = packu(l0, l1);
    }
    __syncthreads();
#pragma unroll
    for (int i = 0; i < 4; i++) {
        int c = ty + i * 8;
        float v0 = tile[tx * 2][c], v1 = tile[tx * 2 + 1][c];
        bf16 h0, l0, h1, l1;
        split1(v0, h0, l0); split1(v1, h1, l1);
        size_t o = (size_t)(c0 + c) * R + r0 + tx * 2;
        *(unsigned*)&thi[o] = packu(h0, h1);
        *(unsigned*)&tlo[o] = packu(l0, l1);
    }
}

// fused: dh = da * silu'(hk); write only DHT hi/lo (transposed)
__global__ void dh_trans_kernel(const float* __restrict__ da,
                                const float* __restrict__ hk,
                                bf16* __restrict__ thi, bf16* __restrict__ tlo,
                                int R, int C)
{
    __shared__ float tile[32][33];
    int tx = threadIdx.x, ty = threadIdx.y;   // 16 x 8
    int r0 = blockIdx.y * 32, c0 = blockIdx.x * 32;
#pragma unroll
    for (int i = 0; i < 4; i++) {
        int r = ty + i * 8;
        size_t o = (size_t)(r0 + r) * C + c0 + tx * 2;
        float2 d = *(const float2*)&da[o];
        float2 h = *(const float2*)&hk[o];
        float s;
        s = sigf(h.x); d.x *= s * (1.0f + h.x * (1.0f - s));
        s = sigf(h.y); d.y *= s * (1.0f + h.y * (1.0f - s));
        tile[r][tx * 2] = d.x;
        tile[r][tx * 2 + 1] = d.y;
    }
    __syncthreads();
#pragma unroll
    for (int i = 0; i < 4; i++) {
        int c = ty + i * 8;
        float v0 = tile[tx * 2][c], v1 = tile[tx * 2 + 1][c];
        bf16 h0, l0, h1, l1;
        split1(v0, h0, l0); split1(v1, h1, l1);
        size_t o = (size_t)(c0 + c) * R + r0 + tx * 2;
        *(unsigned*)&thi[o] = packu(h0, h1);
        *(unsigned*)&tlo[o] = packu(l0, l1);
    }
}

template <bool WF32>
__global__ void l2norm_kernel(float* __restrict__ x,
                              bf16* __restrict__ hi, bf16* __restrict__ lo)
{
    float4* p = (float4*)(x + (size_t)blockIdx.x * DDIM);
    int t = threadIdx.x;
    float4 v = p[t];
    float ss = v.x * v.x + v.y * v.y + v.z * v.z + v.w * v.w;
    __shared__ float red[8];
#pragma unroll
    for (int o = 16; o; o >>= 1) ss += __shfl_xor_sync(~0u, ss, o);
    if ((t & 31) == 0) red[t >> 5] = ss;
    __syncthreads();
    if (t < 8) {
        float s2 = red[t];
#pragma unroll
        for (int o = 4; o; o >>= 1) s2 += __shfl_xor_sync(0xffu, s2, o);
        if (t == 0) red[0] = s2;
    }
    __syncthreads();
    float scale = 1.0f / fmaxf(sqrtf(red[0]), 1e-12f);
    v.x *= scale; v.y *= scale; v.z *= scale; v.w *= scale;
    if (WF32) p[t] = v;
    size_t i = (size_t)blockIdx.x * 256 + t;
    bf16 h0, l0, h1, l1, h2, l2, h3, l3;
    split1(v.x, h0, l0); split1(v.y, h1, l1);
    split1(v.z, h2, l2); split1(v.w, h3, l3);
    ((uint2*)hi)[i] = make_uint2(packu(h0, h1), packu(h2, h3));
    ((uint2*)lo)[i] = make_uint2(packu(l0, l1), packu(l2, l3));
}

// x partial mean: grid (16, 8). xpart[sy][idx] = sum over 256 S entries.
__global__ void xmean_part_kernel(const float* __restrict__ x, float* __restrict__ xp)
{
    int idx = blockIdx.x * 256 + threadIdx.x;   // 0..4095 (b*1024+d)
    int sy = blockIdx.y;
    int b = idx >> 10, d = idx & 1023;
    const float* p = x + ((size_t)b * 2048 + sy * 256) * DDIM + d;
    float s = 0.0f;
#pragma unroll 8
    for (int ss = 0; ss < 256; ss++) s += p[(size_t)ss * DDIM];
    xp[sy * 4096 + idx] = s;
}

__global__ void xmean_fin_kernel(const float* __restrict__ xp, float* __restrict__ xm)
{
    int idx = blockIdx.x * 256 + threadIdx.x;
    float s = 0.0f;
#pragma unroll
    for (int j = 0; j < 8; j++) s += xp[j * 4096 + idx];
    xm[idx] = s * (1.0f / 2048.0f);
}

// warp-per-(gate, j): part[g*1024+j] = sum_b sigmoid(xm[b].W[j] + bias[j])
__global__ void gate_partial_kernel(
    const float* __restrict__ xm,
    const float* __restrict__ gdw, const float* __restrict__ gdb,
    const float* __restrict__ glw, const float* __restrict__ glb,
    const float* __restrict__ gmw, const float* __restrict__ gmb,
    float* __restrict__ part)
{
    int w = (blockIdx.x * 256 + threadIdx.x) >> 5;   // 0..3071
    int lane = threadIdx.x & 31;
    int g = w >> 10, j = w & 1023;
    const float* W = (g == 0) ? gdw : (g == 1) ? glw : gmw;
    const float* bias = (g == 0) ? gdb : (g == 1) ? glb : gmb;
    const float4* wr = (const float4*)(W + (size_t)j * DDIM);
    float bj = bias[j];
    float acc = 0.0f;
#pragma unroll
    for (int b = 0; b < 4; b++) {
        const float4* xr = (const float4*)(xm + b * DDIM);
        float s = 0.0f;
#pragma unroll
        for (int i = 0; i < 8; i++) {
            float4 a = xr[lane + 32 * i];
            float4 ww = wr[lane + 32 * i];
            s += a.x * ww.x + a.y * ww.y + a.z * ww.z + a.w * ww.w;
        }
#pragma unroll
        for (int o = 16; o; o >>= 1) s += __shfl_xor_sync(~0u, s, o);
        if (lane == 0) acc += sigf(s + bj);
    }
    if (lane == 0) part[g * 1024 + j] = acc;
}

// gates[g] = mean over 4*1024. grid 3 blocks x 256 threads.
__global__ void gate_final_kernel(const float* __restrict__ part, float* __restrict__ gates)
{
    int g = blockIdx.x, t = threadIdx.x;
    float v = part[g * 1024 + t] + part[g * 1024 + 256 + t]
            + part[g * 1024 + 512 + t] + part[g * 1024 + 768 + t];
    __shared__ float red[8];
#pragma unroll
    for (int o = 16; o; o >>= 1) v += __shfl_xor_sync(~0u, v, o);
    if ((t & 31) == 0) red[t >> 5] = v;
    __syncthreads();
    if (t < 8) {
        float s2 = red[t];
#pragma unroll
        for (int o = 4; o; o >>= 1) s2 += __shfl_xor_sync(0xffu, s2, o);
        if (t == 0) gates[g] = s2 * (1.0f / 4096.0f);
    }
}

__global__ void update_kernel(
    const float4* __restrict__ w0, const float4* __restrict__ w1,
    const float4* __restrict__ m0, const float4* __restrict__ m1,
    const float4* __restrict__ gg0, const float4* __restrict__ gg0b,
    const float4* __restrict__ gg1, const float4* __restrict__ gg1b,
    const float* __restrict__ gates, float4* __restrict__ out4)
{
    const int HD4 = HDIM * DDIM / 4;
    int i = blockIdx.x * 256 + threadIdx.x;
    float alpha = gates[0], theta = gates[1], eta = gates[2];
    float oma = 1.0f - alpha;
    if (i < HD4) {
        float4 ga = gg0[i], gb = gg0b[i], m = m0[i], w = w0[i], nm, nw;
        nm.x = eta * m.x - theta * (ga.x + gb.x); nw.x = oma * w.x + nm.x;
        nm.y = eta * m.y - theta * (ga.y + gb.y); nw.y = oma * w.y + nm.y;
        nm.z = eta * m.z - theta * (ga.z + gb.z); nw.z = oma * w.z + nm.z;
        nm.w = eta * m.w - theta * (ga.w + gb.w); nw.w = oma * w.w + nm.w;
        out4[2097152 + i] = nw;
        out4[3145728 + i] = nm;
    } else {
        int j = i - HD4;
        float4 ga = gg1[j], gb = gg1b[j], m = m1[j], w = w1[j], nm, nw;
        nm.x = eta * m.x - theta * (ga.x + gb.x); nw.x = oma * w.x + nm.x;
        nm.y = eta * m.y - theta * (ga.y + gb.y); nw.y = oma * w.y + nm.y;
        nm.z = eta * m.z - theta * (ga.z + gb.z); nw.z = oma * w.z + nm.z;
        nm.w = eta * m.w - theta * (ga.w + gb.w); nw.w = oma * w.w + nm.w;
        out4[2621440 + j] = nw;
        out4[3670016 + j] = nm;
    }
}

// ===================== host ================================================

static GemmB3 mk1(const bf16* Ah, const bf16* Al, const bf16* Bh, const bf16* Bl,
                  float* C, bf16* Ch, bf16* Cl)
{
    GemmB3 p{};
    p.b[0] = {Ah, Al, Bh, Bl, C, Ch, Cl};
    return p;
}

extern "C" void kernel_launch(void* const* d_in, const int* in_sizes, int n_in,
                              void* d_out, int out_size)
{
    (void)in_sizes; (void)n_in; (void)out_size;
    const float* x      = (const float*)d_in[0];
    const float* kp_w1  = (const float*)d_in[1];
    const float* kp_w2  = (const float*)d_in[2];
    const float* vp_w1  = (const float*)d_in[3];
    const float* vp_w2  = (const float*)d_in[4];
    const float* qp_w1  = (const float*)d_in[5];
    const float* qp_w2  = (const float*)d_in[6];
    const float* gd_w   = (const float*)d_in[7];
    const float* gd_b   = (const float*)d_in[8];
    const float* gl_w   = (const float*)d_in[9];
    const float* gl_b   = (const float*)d_in[10];
    const float* gm_w   = (const float*)d_in[11];
    const float* gm_b   = (const float*)d_in[12];
    const float* mem_w0 = (const float*)d_in[13];
    const float* mem_w1 = (const float*)d_in[14];
    const float* mom0   = (const float*)d_in[15];
    const float* mom1   = (const float*)d_in[16];
    const float* out_w  = (const float*)d_in[17];
    float* out = (float*)d_out;

    float *keys, *values, *queries, *hk, *pred, *da, *gg0, *gg0b, *gg1, *gg1b;
    float *xpart, *xmean, *gpart, *gates;
    bf16 *bh, *bl;
    cudaGetSymbolAddress((void**)&keys, g_keys);
    cudaGetSymbolAddress((void**)&values, g_values);
    cudaGetSymbolAddress((void**)&queries, g_queries);
    cudaGetSymbolAddress((void**)&hk, g_hk);
    cudaGetSymbolAddress((void**)&pred, g_pred);
    cudaGetSymbolAddress((void**)&da, g_da);
    cudaGetSymbolAddress((void**)&gg0, g_g0);
    cudaGetSymbolAddress((void**)&gg0b, g_g0b);
    cudaGetSymbolAddress((void**)&gg1, g_g1);
    cudaGetSymbolAddress((void**)&gg1b, g_g1b);
    cudaGetSymbolAddress((void**)&xpart, g_xpart);
    cudaGetSymbolAddress((void**)&xmean, g_xmean);
    cudaGetSymbolAddress((void**)&gpart, g_gpart);
    cudaGetSymbolAddress((void**)&gates, g_gates);
    cudaGetSymbolAddress((void**)&bh, g_bfh);
    cudaGetSymbolAddress((void**)&bl, g_bfl);

    cudaFuncSetAttribute(mma_gemm<1, false, true>, cudaFuncAttributeMaxDynamicSharedMemorySize, GSMEM);
    cudaFuncSetAttribute(mma_gemm<1, true, false>, cudaFuncAttributeMaxDynamicSharedMemorySize, GSMEM);
    cudaFuncSetAttribute(mma_gemm<0, false, true>, cudaFuncAttributeMaxDynamicSharedMemorySize, GSMEM);
    cudaFuncSetAttribute(mma_gemm<0, true, false>, cudaFuncAttributeMaxDynamicSharedMemorySize, GSMEM);

    // one-time stream/event resources (no device-memory allocation)
    static cudaStream_t s1 = nullptr;
    static cudaEvent_t evRoot, evW1, evW2, evWM, evW1T, evG, evKQ, evKT, evDP,
        evG1, evEnd;
    if (s1 == nullptr) {
        cudaStreamCreateWithFlags(&s1, cudaStreamNonBlocking);
        cudaEventCreateWithFlags(&evRoot, cudaEventDisableTiming);
        cudaEventCreateWithFlags(&evW1, cudaEventDisableTiming);
        cudaEventCreateWithFlags(&evW2, cudaEventDisableTiming);
        cudaEventCreateWithFlags(&evWM, cudaEventDisableTiming);
        cudaEventCreateWithFlags(&evW1T, cudaEventDisableTiming);
        cudaEventCreateWithFlags(&evG, cudaEventDisableTiming);
        cudaEventCreateWithFlags(&evKQ, cudaEventDisableTiming);
        cudaEventCreateWithFlags(&evKT, cudaEventDisableTiming);
        cudaEventCreateWithFlags(&evDP, cudaEventDisableTiming);
        cudaEventCreateWithFlags(&evG1, cudaEventDisableTiming);
        cudaEventCreateWithFlags(&evEnd, cudaEventDisableTiming);
    }

    dim3 blk(256);
    dim3 ttb(16, 8);

    // ---- fork side stream off the capture-origin (default) stream ----
    cudaEventRecord(evRoot, 0);
    cudaStreamWaitEvent(s1, evRoot, 0);

    // stream0: x conversion
    conv_kernel<<<8192, 256>>>((const float4*)x, bh + O_X, bl + O_X);

    // s1: weight conversions + gates
    {
        Conv3P p{};
        p.c[0] = {(const float4*)kp_w1, bh + O_KP1, bl + O_KP1};
        p.c[1] = {(const float4*)vp_w1, bh + O_VP1, bl + O_VP1};
        p.c[2] = {(const float4*)qp_w1, bh + O_QP1, bl + O_QP1};
        conv3_kernel<<<dim3(1024, 1, 3), 256, 0, s1>>>(p);
    }
    cudaEventRecord(evW1, s1);
    xmean_part_kernel<<<dim3(16, 8), 256, 0, s1>>>(x, xpart);
    xmean_fin_kernel<<<16, 256, 0, s1>>>(xpart, xmean);
    gate_partial_kernel<<<384, 256, 0, s1>>>(xmean, gd_w, gd_b, gl_w, gl_b,
                                             gm_w, gm_b, gpart);

    // stream0: projections layer 1 (z=3)
    cudaStreamWaitEvent(0, evW1, 0);
    {
        GemmB3 p{};
        p.b[0] = {bh + O_X, bl + O_X, bh + O_KP1, bl + O_KP1, nullptr, bh + O_T1, bl + O_T1};
        p.b[1] = {bh + O_X, bl + O_X, bh + O_VP1, bl + O_VP1, nullptr, bh + O_T1B, bl + O_T1B};
        p.b[2] = {bh + O_X, bl + O_X, bh + O_QP1, bl + O_QP1, nullptr, bh + O_T1C, bl + O_T1C};
        mma_gemm<1, false, true><<<dim3(8, 64, 3), blk, GSMEM>>>(p, NTOK, DDIM, DDIM, DDIM, DDIM);
    }

    // s1: rest of gates + remaining conversions
    gate_final_kernel<<<3, 256, 0, s1>>>(gpart, gates);
    cudaEventRecord(evG, s1);
    {
        Conv3P p{};
        p.c[0] = {(const float4*)kp_w2, bh + O_KP2, bl + O_KP2};
        p.c[1] = {(const float4*)vp_w2, bh + O_VP2, bl + O_VP2};
        p.c[2] = {(const float4*)qp_w2, bh + O_QP2, bl + O_QP2};
        conv3_kernel<<<dim3(1024, 1, 3), 256, 0, s1>>>(p);
    }
    cudaEventRecord(evW2, s1);
    conv_kernel<<<2048, 256, 0, s1>>>((const float4*)mem_w0, bh + O_M0, bl + O_M0);
    conv_kernel<<<2048, 256, 0, s1>>>((const float4*)mem_w1, bh + O_M1, bl + O_M1);
    conv_kernel<<<1024, 256, 0, s1>>>((const float4*)out_w, bh + O_OW, bl + O_OW);
    cudaEventRecord(evWM, s1);
    trans_conv_kernel<<<dim3(HDIM / 32, DDIM / 32), ttb, 0, s1>>>(
        mem_w1, bh + O_M1T, bl + O_M1T, DDIM, HDIM);   // w1T [H][D]
    cudaEventRecord(evW1T, s1);

    // s1: W' = out_w @ mem_w1  ([D][H], K=D); out = aq @ W'^T later
    mma_gemm<0, false, true><<<dim3(16, 8, 1), blk, GSMEM, s1>>>(
        mk1(bh + O_OW, bl + O_OW, bh + O_M1T, bl + O_M1T,
            nullptr, bh + O_WP, bl + O_WP),
        DDIM, HDIM, DDIM, DDIM, DDIM);

    // stream0: projections layer 2 (z=3), l2norms
    cudaStreamWaitEvent(0, evW2, 0);
    {
        GemmB3 p{};
        p.b[0] = {bh + O_T1, bl + O_T1, bh + O_KP2, bl + O_KP2, keys, nullptr, nullptr};
        p.b[1] = {bh + O_T1B, bl + O_T1B, bh + O_VP2, bl + O_VP2, values, nullptr, nullptr};
        p.b[2] = {bh + O_T1C, bl + O_T1C, bh + O_QP2, bl + O_QP2, queries, nullptr, nullptr};
        mma_gemm<1, true, false><<<dim3(8, 64, 3), blk, GSMEM>>>(p, NTOK, DDIM, DDIM, DDIM, DDIM);
    }
    l2norm_kernel<false><<<NTOK, 256>>>(keys, bh + O_KEY, bl + O_KEY);
    l2norm_kernel<false><<<NTOK, 256>>>(queries, bh + O_Q, bl + O_Q);
    cudaEventRecord(evKQ, 0);

    // s1: keysT (bf16 pair transpose) + q-chain (aq -> out via W')
    cudaStreamWaitEvent(s1, evKQ, 0);
    trans2_bf16_kernel<<<dim3(DDIM / 32, NTOK / 32), ttb, 0, s1>>>(
        bh + O_KEY, bl + O_KEY, bh + O_KEYT, bl + O_KEYT, NTOK, DDIM);
    cudaEventRecord(evKT, s1);
    mma_gemm<1, false, true><<<dim3(16, 64, 1), blk, GSMEM, s1>>>(
        mk1(bh + O_Q, bl + O_Q, bh + O_M0, bl + O_M0, nullptr, bh + O_AQ, bl + O_AQ),
        NTOK, HDIM, DDIM, DDIM, DDIM);
    mma_gemm<0, true, false><<<dim3(8, 64, 1), blk, GSMEM, s1>>>(
        mk1(bh + O_AQ, bl + O_AQ, bh + O_WP, bl + O_WP, out, nullptr, nullptr),
        NTOK, DDIM, HDIM, HDIM, HDIM);
    cudaEventRecord(evEnd, s1);

    // stream0: loss forward on keys
    cudaStreamWaitEvent(0, evWM, 0);
    mma_gemm<0, true, false><<<dim3(16, 64, 1), blk, GSMEM>>>(
        mk1(bh + O_KEY, bl + O_KEY, bh + O_M0, bl + O_M0, hk, nullptr, nullptr),
        NTOK, HDIM, DDIM, DDIM, DDIM);
    silu_conv_trans_kernel<<<dim3(HDIM / 32, NTOK / 32), ttb>>>(
        hk, bh + O_AK, bl + O_AK, bh + O_AKT, bl + O_AKT, NTOK, HDIM);
    mma_gemm<0, true, false><<<dim3(8, 64, 1), blk, GSMEM>>>(
        mk1(bh + O_AK, bl + O_AK, bh + O_M1, bl + O_M1, pred, nullptr, nullptr),
        NTOK, DDIM, HDIM, HDIM, HDIM);
    dpred_conv_trans_kernel<<<dim3(DDIM / 32, NTOK / 32), ttb>>>(
        pred, values, bh + O_DP, bl + O_DP, bh + O_DPT, bl + O_DPT, NTOK, DDIM);
    cudaEventRecord(evDP, 0);

    // s1 (after q-chain): g1[D,H] = dpredT . akT  (split-K 2 via z)
    cudaStreamWaitEvent(s1, evDP, 0);
    {
        GemmB3 p{};
        p.b[0] = {bh + O_DPT, bl + O_DPT, bh + O_AKT, bl + O_AKT, gg1, nullptr, nullptr};
        p.b[1] = {bh + O_DPT + NTOK / 2, bl + O_DPT + NTOK / 2,
                  bh + O_AKT + NTOK / 2, bl + O_AKT + NTOK / 2, gg1b, nullptr, nullptr};
        mma_gemm<0, true, false><<<dim3(16, 8, 2), blk, GSMEM, s1>>>(
            p, DDIM, HDIM, NTOK / 2, NTOK, NTOK);
    }
    cudaEventRecord(evG1, s1);

    // stream0: da[N,H] = dpred . w1T  (K = D)
    cudaStreamWaitEvent(0, evW1T, 0);
    mma_gemm<0, true, false><<<dim3(16, 64, 1), blk, GSMEM>>>(
        mk1(bh + O_DP, bl + O_DP, bh + O_M1T, bl + O_M1T, da, nullptr, nullptr),
        NTOK, HDIM, DDIM, DDIM, DDIM);
    dh_trans_kernel<<<dim3(HDIM / 32, NTOK / 32), ttb>>>(
        da, hk, bh + O_DHT, bl + O_DHT, NTOK, HDIM);
    // g0[H,D] = dhT . keysT    (K = NTOK, split-K 2 via z)
    cudaStreamWaitEvent(0, evKT, 0);
    {
        GemmB3 p{};
        p.b[0] = {bh + O_DHT, bl + O_DHT, bh + O_KEYT, bl + O_KEYT, gg0, nullptr, nullptr};
        p.b[1] = {bh + O_DHT + NTOK / 2, bl + O_DHT + NTOK / 2,
                  bh + O_KEYT + NTOK / 2, bl + O_KEYT + NTOK / 2, gg0b, nullptr, nullptr};
        mma_gemm<0, true, false><<<dim3(8, 16, 2), blk, GSMEM>>>(
            p, HDIM, DDIM, NTOK / 2, NTOK, NTOK);
    }

    // ---- weight / momentum update (needs gates, g0, g1) ----
    cudaStreamWaitEvent(0, evG, 0);
    cudaStreamWaitEvent(0, evG1, 0);
    update_kernel<<<2 * HDIM * DDIM / 4 / 256, 256>>>(
        (const float4*)mem_w0, (const float4*)mem_w1,
        (const float4*)mom0, (const float4*)mom1,
        (const float4*)gg0, (const float4*)gg0b,
        (const float4*)gg1, (const float4*)gg1b, gates, (float4*)out);

    // ---- join side stream back into the origin stream ----
    cudaStreamWaitEvent(0, evEnd, 0);
}

// round 17
// speedup vs baseline: 2.0590x; 1.9991x over previous
#include <cuda_runtime.h>
#include <cuda_fp16.h>
#include <cstdint>

#define NTOK 8192
#define DDIM 1024
#define HDIM 2048
#define MI 1048576ULL
#define DSCALE 1048576.0f            // 2^20 gradient pre-scale (fp16 subnormal fix)

typedef __half hf;

// ===================== scratch (static device globals) ======================
__device__ float g_keys[NTOK * DDIM];
__device__ float g_values[NTOK * DDIM];
__device__ float g_queries[NTOK * DDIM];
__device__ float g_hk[NTOK * HDIM];
__device__ float g_pred[NTOK * DDIM];
__device__ float g_da[NTOK * HDIM];
__device__ float g_g0[HDIM * DDIM];
__device__ float g_g0b[HDIM * DDIM];
__device__ float g_g1[DDIM * HDIM];
__device__ float g_g1b[DDIM * HDIM];
__device__ float g_xpart[8 * 4 * DDIM];
__device__ float g_xmean[4 * DDIM];
__device__ float g_gpart[3 * DDIM];
__device__ float g_gates[3];

__device__ hf g_hbuf[157 * MI];

// offsets (elements) inside g_hbuf
#define O_X    (0 * MI)
#define O_T1   (8 * MI)
#define O_KEY  (16 * MI)
#define O_KEYT (24 * MI)
#define O_Q    (32 * MI)
#define O_AQ   (40 * MI)   // 16Mi
#define O_WP   (56 * MI)   // W' = out_w @ mem_w1, [D][H], 2Mi
#define O_AK   (64 * MI)   // 16Mi
#define O_AKT  (80 * MI)   // 16Mi
#define O_DP   (96 * MI)
#define O_DPT  (104 * MI)
#define O_DHT  (112 * MI)  // 16Mi
#define O_KP1  (128 * MI)
#define O_KP2  (129 * MI)
#define O_VP1  (130 * MI)
#define O_VP2  (131 * MI)
#define O_QP1  (132 * MI)
#define O_QP2  (133 * MI)
#define O_OW   (134 * MI)
#define O_M0   (135 * MI)  // 2Mi
#define O_M1   (137 * MI)  // 2Mi
#define O_M1T  (139 * MI)  // 2Mi
#define O_T1B  (141 * MI)  // 8Mi
#define O_T1C  (149 * MI)  // 8Mi

// ===================== small helpers =======================================
static __device__ __forceinline__ float sigf(float x) {
    return 1.0f / (1.0f + __expf(-x));
}
static __device__ __forceinline__ float siluf(float x) { return x * sigf(x); }

static __device__ __forceinline__ unsigned pack2(float a, float b) {
    __half2 h = __floats2half2_rn(a, b);
    return *(unsigned*)&h;
}
static __device__ __forceinline__ uint32_t smem_u32(const void* p) {
    uint32_t a;
    asm("{ .reg .u64 t; cvta.to.shared.u64 t, %1; cvt.u32.u64 %0, t; }"
        : "=r"(a) : "l"(p));
    return a;
}

// cp.async / ldmatrix / mma wrappers (sm_80-compatible)
static __device__ __forceinline__ void cp16(uint32_t s, const void* g) {
    asm volatile("cp.async.cg.shared.global [%0], [%1], 16;" :: "r"(s), "l"(g));
}
static __device__ __forceinline__ void cp_commit() {
    asm volatile("cp.async.commit_group;" ::: "memory");
}
template <int N>
static __device__ __forceinline__ void cp_wait() {
    asm volatile("cp.async.wait_group %0;" :: "n"(N) : "memory");
}
static __device__ __forceinline__ void ldm4(uint32_t a, uint32_t& r0, uint32_t& r1,
                                            uint32_t& r2, uint32_t& r3) {
    asm volatile("ldmatrix.sync.aligned.m8n8.x4.shared.b16 {%0,%1,%2,%3}, [%4];"
                 : "=r"(r0), "=r"(r1), "=r"(r2), "=r"(r3) : "r"(a));
}
static __device__ __forceinline__ void mma16816(float* c, const uint32_t* a,
                                                const uint32_t* b) {
    asm volatile(
        "mma.sync.aligned.m16n8k16.row.col.f32.f16.f16.f32 "
        "{%0,%1,%2,%3}, {%4,%5,%6,%7}, {%8,%9}, {%0,%1,%2,%3};"
        : "+f"(c[0]), "+f"(c[1]), "+f"(c[2]), "+f"(c[3])
        : "r"(a[0]), "r"(a[1]), "r"(a[2]), "r"(a[3]), "r"(b[0]), "r"(b[1]));
}

// ===================== batched mma.sync GEMM (fp16) ========================
// Per z-slice: C[M,N] = sum_k A[m,k]*B[n,k]; A/B fp16 row-major with leading
// dims lda/ldb. CTA tile 128x128x64, 8 warps (64x32), 3-stage cp.async,
// single __syncthreads per stage. (R7-proven skeleton, single fp16 term.)
#define BKG 64
#define RSB 144                       // 64 fp16 (128B) + 16B pad
#define TILE_B (128 * RSB)            // 18432
#define STAGE_B (2 * TILE_B)          // 36864
#define NSTAGE 3
#define GSMEM (NSTAGE * STAGE_B)      // 110592

struct GemmB {
    const hf *A, *B;
    float* C;
    hf* Ch;
};
struct GemmB3 { GemmB b[3]; };

template <int EPI, bool WF32, bool WBF>
__global__ __launch_bounds__(256, 1)
void mma_gemm(GemmB3 P, int M, int N, int K, int lda, int ldb)
{
    extern __shared__ char sm[];
    uint32_t sb = smem_u32(sm);
    const GemmB gp = P.b[blockIdx.z];
    const int t = threadIdx.x, lane = t & 31, wid = t >> 5;
    const int row0 = blockIdx.y * 128, col0 = blockIdx.x * 128;

    const hf* gA = gp.A + (size_t)row0 * lda;
    const hf* gB = gp.B + (size_t)col0 * ldb;

    const int r_ld = t >> 3, kc = t & 7;   // 32 rows x 8 16B-chunks per pass

    auto issue = [&](int s) {
        int k0 = s * BKG;
        uint32_t dst = sb + (s % NSTAGE) * STAGE_B + kc * 16;
        const hf* a0 = gA + k0 + kc * 8;
        const hf* b0 = gB + k0 + kc * 8;
#pragma unroll
        for (int j = 0; j < 4; j++) {
            int r = r_ld + 32 * j;
            cp16(dst + r * RSB, a0 + (size_t)r * lda);
            cp16(dst + TILE_B + r * RSB, b0 + (size_t)r * ldb);
        }
        cp_commit();
    };

    const int wm = wid & 1, wn = wid >> 1;
    float acc[4][4][4];
#pragma unroll
    for (int i = 0; i < 4; i++)
#pragma unroll
        for (int j = 0; j < 4; j++)
#pragma unroll
            for (int r = 0; r < 4; r++) acc[i][j][r] = 0.0f;

    const int arow = wm * 64 + (lane & 15);
    const int acolh = (lane >> 4) * 16;
    const int brow = wn * 32 + (lane & 7) + ((lane >> 4) << 3);
    const int bcolh = ((lane >> 3) & 1) * 16;

    const int S = K / BKG;
    issue(0);
    issue(1);
    for (int s = 0; s < S; s++) {
        if (s + 1 < S) cp_wait<1>(); else cp_wait<0>();
        __syncthreads();
        if (s + 2 < S) issue(s + 2);

        uint32_t st = sb + (s % NSTAGE) * STAGE_B;
        uint32_t aA = st, aB = st + TILE_B;
#pragma unroll
        for (int kb = 0; kb < 4; kb++) {
            uint32_t ah[4][4], bh[4][2];
#pragma unroll
            for (int mi = 0; mi < 4; mi++) {
                uint32_t off = (uint32_t)(arow + mi * 16) * RSB + kb * 32 + acolh;
                ldm4(aA + off, ah[mi][0], ah[mi][1], ah[mi][2], ah[mi][3]);
            }
#pragma unroll
            for (int jp = 0; jp < 2; jp++) {
                uint32_t off = (uint32_t)(brow + jp * 16) * RSB + kb * 32 + bcolh;
                uint32_t r0, r1, r2, r3;
                ldm4(aB + off, r0, r1, r2, r3);
                bh[jp * 2][0] = r0; bh[jp * 2][1] = r1;
                bh[jp * 2 + 1][0] = r2; bh[jp * 2 + 1][1] = r3;
            }
#pragma unroll
            for (int mi = 0; mi < 4; mi++)
#pragma unroll
                for (int nj = 0; nj < 4; nj++)
                    mma16816(acc[mi][nj], ah[mi], bh[nj]);
        }
    }

    // epilogue
    const int grow = lane >> 2, gc2 = (lane & 3) * 2;
#pragma unroll
    for (int mi = 0; mi < 4; mi++) {
#pragma unroll
        for (int nj = 0; nj < 4; nj++) {
            int col = col0 + wn * 32 + nj * 8 + gc2;
#pragma unroll
            for (int h = 0; h < 2; h++) {
                size_t row = (size_t)(row0 + wm * 64 + mi * 16 + grow + h * 8);
                float v0 = acc[mi][nj][h * 2], v1 = acc[mi][nj][h * 2 + 1];
                if (EPI == 1) { v0 = siluf(v0); v1 = siluf(v1); }
                if (WF32)
                    *(float2*)&gp.C[row * (size_t)N + col] = make_float2(v0, v1);
                if (WBF)
                    *(unsigned*)&gp.Ch[row * (size_t)N + col] = pack2(v0, v1);
            }
        }
    }
}

// ===================== conversion / elementwise kernels ====================

__global__ void conv_kernel(const float4* __restrict__ src, hf* __restrict__ dst)
{
    int i = blockIdx.x * 256 + threadIdx.x;
    float4 v = src[i];
    ((uint2*)dst)[i] = make_uint2(pack2(v.x, v.y), pack2(v.z, v.w));
}

// z-batched conv of 3 equal-size fp32 arrays
struct Conv3 { const float4* s; hf* d; };
struct Conv3P { Conv3 c[3]; };
__global__ void conv3_kernel(Conv3P P)
{
    Conv3 q = P.c[blockIdx.z];
    int i = blockIdx.x * 256 + threadIdx.x;
    float4 v = q.s[i];
    ((uint2*)q.d)[i] = make_uint2(pack2(v.x, v.y), pack2(v.z, v.w));
}

// transpose + convert: src fp32 [R][C] -> dst fp16 [C][R]
__global__ void trans_conv_kernel(const float* __restrict__ src,
                                  hf* __restrict__ dst, int R, int C)
{
    __shared__ float tile[32][33];
    int tx = threadIdx.x, ty = threadIdx.y;   // 16 x 8
    int r0 = blockIdx.y * 32, c0 = blockIdx.x * 32;
#pragma unroll
    for (int i = 0; i < 4; i++) {
        int r = ty + i * 8;
        float2 v = *(const float2*)&src[(size_t)(r0 + r) * C + c0 + tx * 2];
        tile[r][tx * 2] = v.x;
        tile[r][tx * 2 + 1] = v.y;
    }
    __syncthreads();
#pragma unroll
    for (int i = 0; i < 4; i++) {
        int c = ty + i * 8;
        *(unsigned*)&dst[(size_t)(c0 + c) * R + r0 + tx * 2] =
            pack2(tile[tx * 2][c], tile[tx * 2 + 1][c]);
    }
}

// fp16 transpose: src [R][C] -> dst [C][R]
__global__ void trans_h_kernel(const hf* __restrict__ src,
                               hf* __restrict__ dst, int R, int C)
{
    __shared__ hf tile[32][34];
    int tx = threadIdx.x, ty = threadIdx.y;   // 16 x 8
    int r0 = blockIdx.y * 32, c0 = blockIdx.x * 32;
#pragma unroll
    for (int i = 0; i < 4; i++) {
        int r = ty + i * 8;
        unsigned v = *(const unsigned*)&src[(size_t)(r0 + r) * C + c0 + tx * 2];
        tile[r][tx * 2] = ((hf*)&v)[0];
        tile[r][tx * 2 + 1] = ((hf*)&v)[1];
    }
    __syncthreads();
#pragma unroll
    for (int i = 0; i < 4; i++) {
        int c = ty + i * 8;
        __half2 h = __halves2half2(tile[tx * 2][c], tile[tx * 2 + 1][c]);
        *(unsigned*)&dst[(size_t)(c0 + c) * R + r0 + tx * 2] = *(unsigned*)&h;
    }
}

// fused: ak = silu(hk); write AK fp16 + AKT fp16 (transposed)
__global__ void silu_conv_trans_kernel(const float* __restrict__ src,
                                       hf* __restrict__ d, hf* __restrict__ dt,
                                       int R, int C)
{
    __shared__ float tile[32][33];
    int tx = threadIdx.x, ty = threadIdx.y;   // 16 x 8
    int r0 = blockIdx.y * 32, c0 = blockIdx.x * 32;
#pragma unroll
    for (int i = 0; i < 4; i++) {
        int r = ty + i * 8;
        size_t o = (size_t)(r0 + r) * C + c0 + tx * 2;
        float2 v = *(const float2*)&src[o];
        v.x = siluf(v.x); v.y = siluf(v.y);
        tile[r][tx * 2] = v.x;
        tile[r][tx * 2 + 1] = v.y;
        *(unsigned*)&d[o] = pack2(v.x, v.y);
    }
    __syncthreads();
#pragma unroll
    for (int i = 0; i < 4; i++) {
        int c = ty + i * 8;
        *(unsigned*)&dt[(size_t)(c0 + c) * R + r0 + tx * 2] =
            pack2(tile[tx * 2][c], tile[tx * 2 + 1][c]);
    }
}

// fused: dp = (pred - values)*DPC*DSCALE; write DP fp16 + DPT fp16
__global__ void dpred_conv_trans_kernel(const float* __restrict__ pred,
                                        const float* __restrict__ vals,
                                        hf* __restrict__ d, hf* __restrict__ dt,
                                        int R, int C)
{
    __shared__ float tile[32][33];
    const float cst = (2.0f / (float)((size_t)NTOK * DDIM)) * DSCALE;
    int tx = threadIdx.x, ty = threadIdx.y;   // 16 x 8
    int r0 = blockIdx.y * 32, c0 = blockIdx.x * 32;
#pragma unroll
    for (int i = 0; i < 4; i++) {
        int r = ty + i * 8;
        size_t o = (size_t)(r0 + r) * C + c0 + tx * 2;
        float2 p = *(const float2*)&pred[o];
        float2 v = *(const float2*)&vals[o];
        p.x = (p.x - v.x) * cst; p.y = (p.y - v.y) * cst;
        tile[r][tx * 2] = p.x;
        tile[r][tx * 2 + 1] = p.y;
        *(unsigned*)&d[o] = pack2(p.x, p.y);
    }
    __syncthreads();
#pragma unroll
    for (int i = 0; i < 4; i++) {
        int c = ty + i * 8;
        *(unsigned*)&dt[(size_t)(c0 + c) * R + r0 + tx * 2] =
            pack2(tile[tx * 2][c], tile[tx * 2 + 1][c]);
    }
}

// fused: dh = da * silu'(hk); write only DHT fp16 (transposed)
__global__ void dh_trans_kernel(const float* __restrict__ da,
                                const float* __restrict__ hk,
                                hf* __restrict__ dt, int R, int C)
{
    __shared__ float tile[32][33];
    int tx = threadIdx.x, ty = threadIdx.y;   // 16 x 8
    int r0 = blockIdx.y * 32, c0 = blockIdx.x * 32;
#pragma unroll
    for (int i = 0; i < 4; i++) {
        int r = ty + i * 8;
        size_t o = (size_t)(r0 + r) * C + c0 + tx * 2;
        float2 d = *(const float2*)&da[o];
        float2 h = *(const float2*)&hk[o];
        float s;
        s = sigf(h.x); d.x *= s * (1.0f + h.x * (1.0f - s));
        s = sigf(h.y); d.y *= s * (1.0f + h.y * (1.0f - s));
        tile[r][tx * 2] = d.x;
        tile[r][tx * 2 + 1] = d.y;
    }
    __syncthreads();
#pragma unroll
    for (int i = 0; i < 4; i++) {
        int c = ty + i * 8;
        *(unsigned*)&dt[(size_t)(c0 + c) * R + r0 + tx * 2] =
            pack2(tile[tx * 2][c], tile[tx * 2 + 1][c]);
    }
}

__global__ void l2norm_kernel(float* __restrict__ x, hf* __restrict__ dst)
{
    float4* p = (float4*)(x + (size_t)blockIdx.x * DDIM);
    int t = threadIdx.x;
    float4 v = p[t];
    float ss = v.x * v.x + v.y * v.y + v.z * v.z + v.w * v.w;
    __shared__ float red[8];
#pragma unroll
    for (int o = 16; o; o >>= 1) ss += __shfl_xor_sync(~0u, ss, o);
    if ((t & 31) == 0) red[t >> 5] = ss;
    __syncthreads();
    if (t < 8) {
        float s2 = red[t];
#pragma unroll
        for (int o = 4; o; o >>= 1) s2 += __shfl_xor_sync(0xffu, s2, o);
        if (t == 0) red[0] = s2;
    }
    __syncthreads();
    float scale = 1.0f / fmaxf(sqrtf(red[0]), 1e-12f);
    v.x *= scale; v.y *= scale; v.z *= scale; v.w *= scale;
    size_t i = (size_t)blockIdx.x * 256 + t;
    ((uint2*)dst)[i] = make_uint2(pack2(v.x, v.y), pack2(v.z, v.w));
}

// x partial mean: grid (16, 8). xpart[sy][idx] = sum over 256 S entries.
__global__ void xmean_part_kernel(const float* __restrict__ x, float* __restrict__ xp)
{
    int idx = blockIdx.x * 256 + threadIdx.x;   // 0..4095 (b*1024+d)
    int sy = blockIdx.y;
    int b = idx >> 10, d = idx & 1023;
    const float* p = x + ((size_t)b * 2048 + sy * 256) * DDIM + d;
    float s = 0.0f;
#pragma unroll 8
    for (int ss = 0; ss < 256; ss++) s += p[(size_t)ss * DDIM];
    xp[sy * 4096 + idx] = s;
}

__global__ void xmean_fin_kernel(const float* __restrict__ xp, float* __restrict__ xm)
{
    int idx = blockIdx.x * 256 + threadIdx.x;
    float s = 0.0f;
#pragma unroll
    for (int j = 0; j < 8; j++) s += xp[j * 4096 + idx];
    xm[idx] = s * (1.0f / 2048.0f);
}

// warp-per-(gate, j): part[g*1024+j] = sum_b sigmoid(xm[b].W[j] + bias[j])
__global__ void gate_partial_kernel(
    const float* __restrict__ xm,
    const float* __restrict__ gdw, const float* __restrict__ gdb,
    const float* __restrict__ glw, const float* __restrict__ glb,
    const float* __restrict__ gmw, const float* __restrict__ gmb,
    float* __restrict__ part)
{
    int w = (blockIdx.x * 256 + threadIdx.x) >> 5;   // 0..3071
    int lane = threadIdx.x & 31;
    int g = w >> 10, j = w & 1023;
    const float* W = (g == 0) ? gdw : (g == 1) ? glw : gmw;
    const float* bias = (g == 0) ? gdb : (g == 1) ? glb : gmb;
    const float4* wr = (const float4*)(W + (size_t)j * DDIM);
    float bj = bias[j];
    float acc = 0.0f;
#pragma unroll
    for (int b = 0; b < 4; b++) {
        const float4* xr = (const float4*)(xm + b * DDIM);
        float s = 0.0f;
#pragma unroll
        for (int i = 0; i < 8; i++) {
            float4 a = xr[lane + 32 * i];
            float4 ww = wr[lane + 32 * i];
            s += a.x * ww.x + a.y * ww.y + a.z * ww.z + a.w * ww.w;
        }
#pragma unroll
        for (int o = 16; o; o >>= 1) s += __shfl_xor_sync(~0u, s, o);
        if (lane == 0) acc += sigf(s + bj);
    }
    if (lane == 0) part[g * 1024 + j] = acc;
}

// gates[g] = mean over 4*1024. grid 3 blocks x 256 threads.
__global__ void gate_final_kernel(const float* __restrict__ part, float* __restrict__ gates)
{
    int g = blockIdx.x, t = threadIdx.x;
    float v = part[g * 1024 + t] + part[g * 1024 + 256 + t]
            + part[g * 1024 + 512 + t] + part[g * 1024 + 768 + t];
    __shared__ float red[8];
#pragma unroll
    for (int o = 16; o; o >>= 1) v += __shfl_xor_sync(~0u, v, o);
    if ((t & 31) == 0) red[t >> 5] = v;
    __syncthreads();
    if (t < 8) {
        float s2 = red[t];
#pragma unroll
        for (int o = 4; o; o >>= 1) s2 += __shfl_xor_sync(0xffu, s2, o);
        if (t == 0) gates[g] = s2 * (1.0f / 4096.0f);
    }
}

// gradients carry DSCALE; theta is divided by DSCALE here.
__global__ void update_kernel(
    const float4* __restrict__ w0, const float4* __restrict__ w1,
    const float4* __restrict__ m0, const float4* __restrict__ m1,
    const float4* __restrict__ gg0, const float4* __restrict__ gg0b,
    const float4* __restrict__ gg1, const float4* __restrict__ gg1b,
    const float* __restrict__ gates, float4* __restrict__ out4)
{
    const int HD4 = HDIM * DDIM / 4;
    int i = blockIdx.x * 256 + threadIdx.x;
    float alpha = gates[0], theta = gates[1] * (1.0f / DSCALE), eta = gates[2];
    float oma = 1.0f - alpha;
    if (i < HD4) {
        float4 ga = gg0[i], gb = gg0b[i], m = m0[i], w = w0[i], nm, nw;
        nm.x = eta * m.x - theta * (ga.x + gb.x); nw.x = oma * w.x + nm.x;
        nm.y = eta * m.y - theta * (ga.y + gb.y); nw.y = oma * w.y + nm.y;
        nm.z = eta * m.z - theta * (ga.z + gb.z); nw.z = oma * w.z + nm.z;
        nm.w = eta * m.w - theta * (ga.w + gb.w); nw.w = oma * w.w + nm.w;
        out4[2097152 + i] = nw;
        out4[3145728 + i] = nm;
    } else {
        int j = i - HD4;
        float4 ga = gg1[j], gb = gg1b[j], m = m1[j], w = w1[j], nm, nw;
        nm.x = eta * m.x - theta * (ga.x + gb.x); nw.x = oma * w.x + nm.x;
        nm.y = eta * m.y - theta * (ga.y + gb.y); nw.y = oma * w.y + nm.y;
        nm.z = eta * m.z - theta * (ga.z + gb.z); nw.z = oma * w.z + nm.z;
        nm.w = eta * m.w - theta * (ga.w + gb.w); nw.w = oma * w.w + nm.w;
        out4[2621440 + j] = nw;
        out4[3670016 + j] = nm;
    }
}

// ===================== host ================================================

static GemmB3 mk1(const hf* A, const hf* B, float* C, hf* Ch)
{
    GemmB3 p{};
    p.b[0] = {A, B, C, Ch};
    return p;
}

extern "C" void kernel_launch(void* const* d_in, const int* in_sizes, int n_in,
                              void* d_out, int out_size)
{
    (void)in_sizes; (void)n_in; (void)out_size;
    const float* x      = (const float*)d_in[0];
    const float* kp_w1  = (const float*)d_in[1];
    const float* kp_w2  = (const float*)d_in[2];
    const float* vp_w1  = (const float*)d_in[3];
    const float* vp_w2  = (const float*)d_in[4];
    const float* qp_w1  = (const float*)d_in[5];
    const float* qp_w2  = (const float*)d_in[6];
    const float* gd_w   = (const float*)d_in[7];
    const float* gd_b   = (const float*)d_in[8];
    const float* gl_w   = (const float*)d_in[9];
    const float* gl_b   = (const float*)d_in[10];
    const float* gm_w   = (const float*)d_in[11];
    const float* gm_b   = (const float*)d_in[12];
    const float* mem_w0 = (const float*)d_in[13];
    const float* mem_w1 = (const float*)d_in[14];
    const float* mom0   = (const float*)d_in[15];
    const float* mom1   = (const float*)d_in[16];
    const float* out_w  = (const float*)d_in[17];
    float* out = (float*)d_out;

    float *keys, *values, *queries, *hk, *pred, *da, *gg0, *gg0b, *gg1, *gg1b;
    float *xpart, *xmean, *gpart, *gates;
    hf* hb;
    cudaGetSymbolAddress((void**)&keys, g_keys);
    cudaGetSymbolAddress((void**)&values, g_values);
    cudaGetSymbolAddress((void**)&queries, g_queries);
    cudaGetSymbolAddress((void**)&hk, g_hk);
    cudaGetSymbolAddress((void**)&pred, g_pred);
    cudaGetSymbolAddress((void**)&da, g_da);
    cudaGetSymbolAddress((void**)&gg0, g_g0);
    cudaGetSymbolAddress((void**)&gg0b, g_g0b);
    cudaGetSymbolAddress((void**)&gg1, g_g1);
    cudaGetSymbolAddress((void**)&gg1b, g_g1b);
    cudaGetSymbolAddress((void**)&xpart, g_xpart);
    cudaGetSymbolAddress((void**)&xmean, g_xmean);
    cudaGetSymbolAddress((void**)&gpart, g_gpart);
    cudaGetSymbolAddress((void**)&gates, g_gates);
    cudaGetSymbolAddress((void**)&hb, g_hbuf);

    cudaFuncSetAttribute(mma_gemm<1, false, true>, cudaFuncAttributeMaxDynamicSharedMemorySize, GSMEM);
    cudaFuncSetAttribute(mma_gemm<1, true, false>, cudaFuncAttributeMaxDynamicSharedMemorySize, GSMEM);
    cudaFuncSetAttribute(mma_gemm<0, false, true>, cudaFuncAttributeMaxDynamicSharedMemorySize, GSMEM);
    cudaFuncSetAttribute(mma_gemm<0, true, false>, cudaFuncAttributeMaxDynamicSharedMemorySize, GSMEM);

    // one-time stream/event resources (no device-memory allocation)
    static cudaStream_t s1 = nullptr;
    static cudaEvent_t evRoot, evW1, evW2, evWM, evW1T, evG, evKQ, evKT, evDP,
        evG1, evEnd;
    if (s1 == nullptr) {
        cudaStreamCreateWithFlags(&s1, cudaStreamNonBlocking);
        cudaEventCreateWithFlags(&evRoot, cudaEventDisableTiming);
        cudaEventCreateWithFlags(&evW1, cudaEventDisableTiming);
        cudaEventCreateWithFlags(&evW2, cudaEventDisableTiming);
        cudaEventCreateWithFlags(&evWM, cudaEventDisableTiming);
        cudaEventCreateWithFlags(&evW1T, cudaEventDisableTiming);
        cudaEventCreateWithFlags(&evG, cudaEventDisableTiming);
        cudaEventCreateWithFlags(&evKQ, cudaEventDisableTiming);
        cudaEventCreateWithFlags(&evKT, cudaEventDisableTiming);
        cudaEventCreateWithFlags(&evDP, cudaEventDisableTiming);
        cudaEventCreateWithFlags(&evG1, cudaEventDisableTiming);
        cudaEventCreateWithFlags(&evEnd, cudaEventDisableTiming);
    }

    dim3 blk(256);
    dim3 ttb(16, 8);

    // ---- fork side stream off the capture-origin (default) stream ----
    cudaEventRecord(evRoot, 0);
    cudaStreamWaitEvent(s1, evRoot, 0);

    // stream0: x conversion
    conv_kernel<<<8192, 256>>>((const float4*)x, hb + O_X);

    // s1: weight conversions + gates
    {
        Conv3P p{};
        p.c[0] = {(const float4*)kp_w1, hb + O_KP1};
        p.c[1] = {(const float4*)vp_w1, hb + O_VP1};
        p.c[2] = {(const float4*)qp_w1, hb + O_QP1};
        conv3_kernel<<<dim3(1024, 1, 3), 256, 0, s1>>>(p);
    }
    cudaEventRecord(evW1, s1);
    xmean_part_kernel<<<dim3(16, 8), 256, 0, s1>>>(x, xpart);
    xmean_fin_kernel<<<16, 256, 0, s1>>>(xpart, xmean);
    gate_partial_kernel<<<384, 256, 0, s1>>>(xmean, gd_w, gd_b, gl_w, gl_b,
                                             gm_w, gm_b, gpart);

    // stream0: projections layer 1 (z=3)
    cudaStreamWaitEvent(0, evW1, 0);
    {
        GemmB3 p{};
        p.b[0] = {hb + O_X, hb + O_KP1, nullptr, hb + O_T1};
        p.b[1] = {hb + O_X, hb + O_VP1, nullptr, hb + O_T1B};
        p.b[2] = {hb + O_X, hb + O_QP1, nullptr, hb + O_T1C};
        mma_gemm<1, false, true><<<dim3(8, 64, 3), blk, GSMEM>>>(p, NTOK, DDIM, DDIM, DDIM, DDIM);
    }

    // s1: rest of gates + remaining conversions
    gate_final_kernel<<<3, 256, 0, s1>>>(gpart, gates);
    cudaEventRecord(evG, s1);
    {
        Conv3P p{};
        p.c[0] = {(const float4*)kp_w2, hb + O_KP2};
        p.c[1] = {(const float4*)vp_w2, hb + O_VP2};
        p.c[2] = {(const float4*)qp_w2, hb + O_QP2};
        conv3_kernel<<<dim3(1024, 1, 3), 256, 0, s1>>>(p);
    }
    cudaEventRecord(evW2, s1);
    conv_kernel<<<2048, 256, 0, s1>>>((const float4*)mem_w0, hb + O_M0);
    conv_kernel<<<2048, 256, 0, s1>>>((const float4*)mem_w1, hb + O_M1);
    conv_kernel<<<1024, 256, 0, s1>>>((const float4*)out_w, hb + O_OW);
    cudaEventRecord(evWM, s1);
    trans_conv_kernel<<<dim3(HDIM / 32, DDIM / 32), ttb, 0, s1>>>(
        mem_w1, hb + O_M1T, DDIM, HDIM);   // w1T [H][D]
    cudaEventRecord(evW1T, s1);

    // s1: W' = out_w @ mem_w1  ([D][H], K=D); out = aq @ W'^T later
    mma_gemm<0, false, true><<<dim3(16, 8, 1), blk, GSMEM, s1>>>(
        mk1(hb + O_OW, hb + O_M1T, nullptr, hb + O_WP),
        DDIM, HDIM, DDIM, DDIM, DDIM);

    // stream0: projections layer 2 (z=3), l2norms
    cudaStreamWaitEvent(0, evW2, 0);
    {
        GemmB3 p{};
        p.b[0] = {hb + O_T1, hb + O_KP2, keys, nullptr};
        p.b[1] = {hb + O_T1B, hb + O_VP2, values, nullptr};
        p.b[2] = {hb + O_T1C, hb + O_QP2, queries, nullptr};
        mma_gemm<1, true, false><<<dim3(8, 64, 3), blk, GSMEM>>>(p, NTOK, DDIM, DDIM, DDIM, DDIM);
    }
    l2norm_kernel<<<NTOK, 256>>>(keys, hb + O_KEY);
    l2norm_kernel<<<NTOK, 256>>>(queries, hb + O_Q);
    cudaEventRecord(evKQ, 0);

    // s1: keysT (fp16 transpose) + q-chain (aq -> out via W')
    cudaStreamWaitEvent(s1, evKQ, 0);
    trans_h_kernel<<<dim3(DDIM / 32, NTOK / 32), ttb, 0, s1>>>(
        hb + O_KEY, hb + O_KEYT, NTOK, DDIM);
    cudaEventRecord(evKT, s1);
    mma_gemm<1, false, true><<<dim3(16, 64, 1), blk, GSMEM, s1>>>(
        mk1(hb + O_Q, hb + O_M0, nullptr, hb + O_AQ),
        NTOK, HDIM, DDIM, DDIM, DDIM);
    mma_gemm<0, true, false><<<dim3(8, 64, 1), blk, GSMEM, s1>>>(
        mk1(hb + O_AQ, hb + O_WP, out, nullptr),
        NTOK, DDIM, HDIM, HDIM, HDIM);
    cudaEventRecord(evEnd, s1);

    // stream0: loss forward on keys
    cudaStreamWaitEvent(0, evWM, 0);
    mma_gemm<0, true, false><<<dim3(16, 64, 1), blk, GSMEM>>>(
        mk1(hb + O_KEY, hb + O_M0, hk, nullptr),
        NTOK, HDIM, DDIM, DDIM, DDIM);
    silu_conv_trans_kernel<<<dim3(HDIM / 32, NTOK / 32), ttb>>>(
        hk, hb + O_AK, hb + O_AKT, NTOK, HDIM);
    mma_gemm<0, true, false><<<dim3(8, 64, 1), blk, GSMEM>>>(
        mk1(hb + O_AK, hb + O_M1, pred, nullptr),
        NTOK, DDIM, HDIM, HDIM, HDIM);
    dpred_conv_trans_kernel<<<dim3(DDIM / 32, NTOK / 32), ttb>>>(
        pred, values, hb + O_DP, hb + O_DPT, NTOK, DDIM);
    cudaEventRecord(evDP, 0);

    // s1 (after q-chain): g1[D,H] = dpredT . akT  (split-K 2 via z)
    cudaStreamWaitEvent(s1, evDP, 0);
    {
        GemmB3 p{};
        p.b[0] = {hb + O_DPT, hb + O_AKT, gg1, nullptr};
        p.b[1] = {hb + O_DPT + NTOK / 2, hb + O_AKT + NTOK / 2, gg1b, nullptr};
        mma_gemm<0, true, false><<<dim3(16, 8, 2), blk, GSMEM, s1>>>(
            p, DDIM, HDIM, NTOK / 2, NTOK, NTOK);
    }
    cudaEventRecord(evG1, s1);

    // stream0: da[N,H] = dpred . w1T  (K = D)
    cudaStreamWaitEvent(0, evW1T, 0);
    mma_gemm<0, true, false><<<dim3(16, 64, 1), blk, GSMEM>>>(
        mk1(hb + O_DP, hb + O_M1T, da, nullptr),
        NTOK, HDIM, DDIM, DDIM, DDIM);
    dh_trans_kernel<<<dim3(HDIM / 32, NTOK / 32), ttb>>>(
        da, hk, hb + O_DHT, NTOK, HDIM);
    // g0[H,D] = dhT . keysT    (K = NTOK, split-K 2 via z)
    cudaStreamWaitEvent(0, evKT, 0);
    {
        GemmB3 p{};
        p.b[0] = {hb + O_DHT, hb + O_KEYT, gg0, nullptr};
        p.b[1] = {hb + O_DHT + NTOK / 2, hb + O_KEYT + NTOK / 2, gg0b, nullptr};
        mma_gemm<0, true, false><<<dim3(8, 16, 2), blk, GSMEM>>>(
            p, HDIM, DDIM, NTOK / 2, NTOK, NTOK);
    }

    // ---- weight / momentum update (needs gates, g0, g1) ----
    cudaStreamWaitEvent(0, evG, 0);
    cudaStreamWaitEvent(0, evG1, 0);
    update_kernel<<<2 * HDIM * DDIM / 4 / 256, 256>>>(
        (const float4*)mem_w0, (const float4*)mem_w1,
        (const float4*)mom0, (const float4*)mom1,
        (const float4*)gg0, (const float4*)gg0b,
        (const float4*)gg1, (const float4*)gg1b, gates, (float4*)out);

    // ---- join side stream back into the origin stream ----
    cudaStreamWaitEvent(0, evEnd, 0);
}